// round 11
// baseline (speedup 1.0000x reference)
#include <cuda_runtime.h>
#include <math.h>

#define HTOT 87296
#define NANCH 261888
#define PRE_NMS_N 6000
#define POST_NMS_N 300
#define NEGV -1000000000.0f
#define TIE_CAP 16384
#define STTOT 21824

typedef unsigned long long u64;
typedef unsigned int u32;

// ---------------- device scratch ----------------
static __device__ __align__(16) float g_h[(size_t)256 * HTOT];
static __device__ __align__(16) float g_V[(size_t)16 * 256 * STTOT];  // winograd V; reused in-place as M
static __device__ __align__(16) float g_U[(size_t)16 * 256 * 256];    // transformed weights (scalar, no dup)
#define g_M g_V   // safe alias: w2 block (stb,k) reads V[k][:,st-tile] fully before writing M[k][:,st-tile]
static __device__ float4 g_boxes[NANCH];
static __device__ float  g_scores[NANCH];
static __device__ float4 g_tb[PRE_NMS_N];
static __device__ float  g_ts[PRE_NMS_N];
static __device__ int    g_ti[PRE_NMS_N];
static __device__ unsigned int g_hist[256];
static __device__ unsigned int g_prefix, g_above, g_remain;
static __device__ int g_ctr, g_tiectr;
static __device__ int g_ties[TIE_CAP];

// ---------------- f32x2 / cp.async helpers ----------------
__device__ __forceinline__ void ffma2(u64& d, u64 a, u64 b) {
    asm("fma.rn.f32x2 %0, %1, %2, %0;" : "+l"(d) : "l"(a), "l"(b));
}
__device__ __forceinline__ u64 dup2(float v) {
    u64 r;
    asm("mov.b64 %0, {%1, %2};" : "=l"(r) : "f"(v), "f"(v));
    return r;
}
__device__ __forceinline__ void cpasync16(u32 saddr, const void* gptr) {
    asm volatile("cp.async.cg.shared.global [%0], [%1], 16;" :: "r"(saddr), "l"(gptr));
}
__device__ __forceinline__ void cp_commit() {
    asm volatile("cp.async.commit_group;");
}

__global__ void dummy_k() {}

// ---------------- W0: weight transform U = G w G^T (scalar layout) ------
__global__ __launch_bounds__(256) void w0_wtrans(const float* __restrict__ w) {
    int oc = blockIdx.x;
    int ic = threadIdx.x;
    const float* g = w + ((size_t)oc * 256 + ic) * 9;
    float g0 = g[0], g1 = g[1], g2 = g[2];
    float g3 = g[3], g4 = g[4], g5 = g[5];
    float g6 = g[6], g7 = g[7], g8 = g[8];

    float T[4][3];
    T[0][0] = g0; T[0][1] = g1; T[0][2] = g2;
    T[1][0] = 0.5f * (g0 + g3 + g6); T[1][1] = 0.5f * (g1 + g4 + g7); T[1][2] = 0.5f * (g2 + g5 + g8);
    T[2][0] = 0.5f * (g0 - g3 + g6); T[2][1] = 0.5f * (g1 - g4 + g7); T[2][2] = 0.5f * (g2 - g5 + g8);
    T[3][0] = g6; T[3][1] = g7; T[3][2] = g8;

#pragma unroll
    for (int r = 0; r < 4; r++) {
        float u0 = T[r][0];
        float u1 = 0.5f * (T[r][0] + T[r][1] + T[r][2]);
        float u2 = 0.5f * (T[r][0] - T[r][1] + T[r][2]);
        float u3 = T[r][2];
        float uv[4] = {u0, u1, u2, u3};
#pragma unroll
        for (int c = 0; c < 4; c++) {
            int k = r * 4 + c;
            g_U[((size_t)k * 256 + ic) * 256 + oc] = uv[c];
        }
    }
}

// ---------------- W1: input transform V = B^T d B (smem-staged) ----------
template<int W>
__device__ __forceinline__ void w1_level(
    const float* __restrict__ x, int stoff, int st0, int icg, int t, float* Xs)
{
    constexpr int SW  = W / 2;
    constexpr int LSW = (W == 256) ? 7 : (W == 128) ? 6 : (W == 64) ? 5 : (W == 32) ? 4 : 3;
    constexpr int NSY = (64 > SW) ? (64 / SW) : 1;   // supertile rows per block
    constexpr int NCX = (64 < SW) ? 64 : SW;         // supertile cols per block
    constexpr int R   = 2 * NSY + 2;                 // staged pixel rows
    constexpr int C   = 2 * NCX + 2;                 // staged pixel cols
    constexpr int LSL = (SW >= 64) ? 6 : LSW;

    const int sidx0 = st0 - stoff;
    const int sy0 = sidx0 >> LSW;
    const int sx0 = sidx0 & (SW - 1);
    const int gy0 = 2 * sy0 - 1;
    const int gx0 = 2 * sx0 - 1;

    // stage bounding region for 4 input channels, coalesced rows, zero-padded
    for (int i = t; i < 4 * R * C; i += 256) {
        int icc = i / (R * C);
        int rem = i - icc * (R * C);
        int ry  = rem / C;
        int rx  = rem - ry * C;
        int gy  = gy0 + ry;
        int gx  = gx0 + rx;
        float v = 0.f;
        if (gy >= 0 && gy < W && gx >= 0 && gx < W)
            v = x[(size_t)(icg * 4 + icc) * W * W + gy * W + gx];
        Xs[i] = v;
    }
    __syncthreads();

    const int stl = t & 63;
    const int icl = t >> 6;
    const int syl = stl >> LSL;
    const int sxl = stl & ((1 << LSL) - 1);
    const float* Xp = Xs + icl * (R * C) + (2 * syl) * C + 2 * sxl;

    float d[4][4];
#pragma unroll
    for (int r = 0; r < 4; r++)
#pragma unroll
        for (int c = 0; c < 4; c++)
            d[r][c] = Xp[r * C + c];

    float e[4][4];
#pragma unroll
    for (int c = 0; c < 4; c++) {
        e[0][c] = d[0][c] - d[2][c];
        e[1][c] = d[1][c] + d[2][c];
        e[2][c] = d[2][c] - d[1][c];
        e[3][c] = d[1][c] - d[3][c];
    }
    float V[4][4];
#pragma unroll
    for (int r = 0; r < 4; r++) {
        V[r][0] = e[r][0] - e[r][2];
        V[r][1] = e[r][1] + e[r][2];
        V[r][2] = e[r][2] - e[r][1];
        V[r][3] = e[r][1] - e[r][3];
    }
    const int st = st0 + stl;
    size_t base = (size_t)(icg * 4 + icl) * STTOT + st;
#pragma unroll
    for (int r = 0; r < 4; r++)
#pragma unroll
        for (int c = 0; c < 4; c++)
            g_V[(size_t)(r * 4 + c) * 256 * STTOT + base] = V[r][c];
}

__global__ __launch_bounds__(256) void w1_xtrans(
    const float* __restrict__ p2, const float* __restrict__ p3,
    const float* __restrict__ p4, const float* __restrict__ p5,
    const float* __restrict__ p6)
{
    __shared__ float Xs[2080];   // max over levels: 4*4*130
    int st0 = blockIdx.x * 64;
    int icg = blockIdx.y;
    int t = threadIdx.x;
    if (st0 < 16384)      w1_level<256>(p2, 0,     st0, icg, t, Xs);
    else if (st0 < 20480) w1_level<128>(p3, 16384, st0, icg, t, Xs);
    else if (st0 < 21504) w1_level<64> (p4, 20480, st0, icg, t, Xs);
    else if (st0 < 21760) w1_level<32> (p5, 21504, st0, icg, t, Xs);
    else                  w1_level<16> (p6, 21760, st0, icg, t, Xs);
}

// ---------------- W2: pure GEMM per k, 3-stage cp.async pipeline ----------
// block = (stb, k): 256 oc x 64 st x 256 ic. thread = 8 oc x 8 st.
// buffer: V 16x64 (4KB) + U 16x256 scalar (16KB) = 5120 floats; 3 buffers.
#define W2_BUF 5120
#define W2_SMEM (3 * W2_BUF * 4)

__global__ __launch_bounds__(256, 2) void w2_gemm_k() {
    extern __shared__ __align__(16) float sm[];

    const int t   = threadIdx.x;
    const int stb = blockIdx.x;    // 0..340
    const int k   = blockIdx.y;    // 0..15
    const int st0 = stb * 64;
    const int thr_oc = t >> 3;     // 0..31
    const int thr_st = t & 7;      // 0..7

    u64 m[8][4];
#pragma unroll
    for (int o = 0; o < 8; o++)
#pragma unroll
        for (int s = 0; s < 4; s++) m[o][s] = 0ull;

    const float* Vbase = g_V + (size_t)k * 256 * STTOT + st0;
    const float* Ubase = g_U + (size_t)k * 256 * 256;

    // staging mapping
    const int vr = t >> 4;              // ic-local 0..15
    const int vcofs = (t & 15) * 4;     // col 0..60

    u32 smbase = (u32)__cvta_generic_to_shared(sm);

#define W2_PREFETCH(chunk, buf)                                                  \
    do {                                                                         \
        u32 bs_ = smbase + (buf) * (W2_BUF * 4);                                 \
        cpasync16(bs_ + (vr * 64 + vcofs) * 4,                                   \
                  Vbase + (size_t)((chunk) * 16 + vr) * STTOT + vcofs);          \
        const float* us_ = Ubase + (size_t)(chunk) * 16 * 256;                   \
        u32 ud_ = bs_ + 1024 * 4;                                                \
        _Pragma("unroll")                                                        \
        for (int j = 0; j < 4; j++)                                              \
            cpasync16(ud_ + (t + j * 256) * 16, us_ + (size_t)(t + j * 256) * 4);\
        cp_commit();                                                             \
    } while (0)

    W2_PREFETCH(0, 0);
    W2_PREFETCH(1, 1);
    W2_PREFETCH(2, 2);

    for (int c = 0; c < 16; c++) {
        if (c <= 13)      asm volatile("cp.async.wait_group 2;");
        else if (c == 14) asm volatile("cp.async.wait_group 1;");
        else              asm volatile("cp.async.wait_group 0;");
        __syncthreads();

        const float* bs = sm + (c % 3) * W2_BUF;
        const float* Vc = bs;
        const float* Uc = bs + 1024;
#pragma unroll
        for (int ic = 0; ic < 16; ic++) {
            const ulonglong2* vp = (const ulonglong2*)(Vc + ic * 64 + thr_st * 8);
            ulonglong2 va = vp[0], vb = vp[1];
            u64 v[4] = {va.x, va.y, vb.x, vb.y};
            const float4* up = (const float4*)(Uc + ic * 256 + thr_oc * 8);
            float4 ua4 = up[0], ub4 = up[1];
            u64 u[8];
            u[0] = dup2(ua4.x); u[1] = dup2(ua4.y);
            u[2] = dup2(ua4.z); u[3] = dup2(ua4.w);
            u[4] = dup2(ub4.x); u[5] = dup2(ub4.y);
            u[6] = dup2(ub4.z); u[7] = dup2(ub4.w);
#pragma unroll
            for (int o = 0; o < 8; o++)
#pragma unroll
                for (int s = 0; s < 4; s++) ffma2(m[o][s], v[s], u[o]);
        }
        __syncthreads();
        if (c + 3 < 16) W2_PREFETCH(c + 3, (c + 3) % 3);
    }

    // all V reads for this (k, st-tile) are done; in-place write M over V
#pragma unroll
    for (int o = 0; o < 8; o++) {
        int oc = thr_oc * 8 + o;
        u64* mp = (u64*)(g_M + ((size_t)k * 256 + oc) * STTOT + st0 + thr_st * 8);
        ulonglong2 s0, s1;
        s0.x = m[o][0]; s0.y = m[o][1];
        s1.x = m[o][2]; s1.y = m[o][3];
        *(ulonglong2*)mp = s0;
        *(ulonglong2*)(mp + 2) = s1;
    }
}

// ---------------- W3: output transform A^T M A + bias + relu ----------------
__global__ __launch_bounds__(256) void w3_otrans(const float* __restrict__ bias) {
    const int stb = blockIdx.x;    // 0..340
    const int ocg = blockIdx.y;    // 0..15
    const int t = threadIdx.x;
    const int stl = t & 63;
    const int ocl = t >> 6;
    const int st0 = stb * 64;
    const int st  = st0 + stl;

    int W, lsw, stoff, pixoff;
    if (st0 < 16384)       { W = 256; lsw = 7; stoff = 0;     pixoff = 0; }
    else if (st0 < 20480)  { W = 128; lsw = 6; stoff = 16384; pixoff = 65536; }
    else if (st0 < 21504)  { W = 64;  lsw = 5; stoff = 20480; pixoff = 81920; }
    else if (st0 < 21760)  { W = 32;  lsw = 4; stoff = 21504; pixoff = 86016; }
    else                   { W = 16;  lsw = 3; stoff = 21760; pixoff = 87040; }
    int SW = W >> 1;

    int sidx = st - stoff;
    int sy = sidx >> lsw;
    int sx = sidx & (SW - 1);

#pragma unroll
    for (int o4 = 0; o4 < 4; o4++) {
        int oc = ocg * 16 + ocl * 4 + o4;
        const float* Mp = g_M + (size_t)oc * STTOT + st;
        float Mv[16];
#pragma unroll
        for (int kk = 0; kk < 16; kk++)
            Mv[kk] = Mp[(size_t)kk * 256 * STTOT];

        float e0[4], e1[4];
#pragma unroll
        for (int c = 0; c < 4; c++) {
            e0[c] = Mv[c] + Mv[4 + c] + Mv[8 + c];
            e1[c] = Mv[4 + c] - Mv[8 + c] - Mv[12 + c];
        }
        float o00 = e0[0] + e0[1] + e0[2];
        float o01 = e0[1] - e0[2] - e0[3];
        float o10 = e1[0] + e1[1] + e1[2];
        float o11 = e1[1] - e1[2] - e1[3];

        float bv = bias[oc];
        float* hp = g_h + (size_t)oc * HTOT + pixoff;
        float2 r0, r1;
        r0.x = fmaxf(o00 + bv, 0.f);
        r0.y = fmaxf(o01 + bv, 0.f);
        r1.x = fmaxf(o10 + bv, 0.f);
        r1.y = fmaxf(o11 + bv, 0.f);
        *(float2*)&hp[(2 * sy) * W + 2 * sx]     = r0;
        *(float2*)&hp[(2 * sy + 1) * W + 2 * sx] = r1;
    }
}

// ---------------- heads: 1x1 convs + softmax + decode + min-size ----------------
__global__ __launch_bounds__(128) void heads_decode(
    const float* __restrict__ lw, const float* __restrict__ lb,
    const float* __restrict__ sw, const float* __restrict__ sb)
{
    __shared__ float WL[12][256];
    __shared__ float WS[6][256];
    __shared__ float BL[12], BS[6];
    const int t = threadIdx.x;
    for (int i = t; i < 12 * 256; i += 128) WL[i >> 8][i & 255] = lw[i];
    for (int i = t; i < 6 * 256; i += 128)  WS[i >> 8][i & 255] = sw[i];
    if (t < 12) BL[t] = lb[t];
    if (t < 6)  BS[t] = sb[t];
    __syncthreads();

    const int pix = blockIdx.x * 128 + t;
    int lvl;
    if (pix < 65536) lvl = 0;
    else if (pix < 81920) lvl = 1;
    else if (pix < 86016) lvl = 2;
    else if (pix < 87040) lvl = 3;
    else lvl = 4;
    const int offs[5] = {0, 65536, 81920, 86016, 87040};
    const int lp   = pix - offs[lvl];
    const int lw2  = 8 - lvl;
    const int row  = lp >> lw2;
    const int col  = lp & ((1 << lw2) - 1);
    const int strd = 4 << lvl;

    float acc[18];
#pragma unroll
    for (int j = 0; j < 12; j++) acc[j] = BL[j];
#pragma unroll
    for (int j = 0; j < 6; j++)  acc[12 + j] = BS[j];

    const float* hp = g_h + pix;
#pragma unroll 4
    for (int ic = 0; ic < 256; ic++) {
        float v = hp[(size_t)ic * HTOT];
#pragma unroll
        for (int j = 0; j < 12; j++) acc[j] = fmaf(WL[j][ic], v, acc[j]);
#pragma unroll
        for (int j = 0; j < 6; j++)  acc[12 + j] = fmaf(WS[j][ic], v, acc[12 + j]);
    }

    const float y  = (float)(row * strd);
    const float xx = (float)(col * strd);
    const float sr[3] = {0.70710678118654752f, 1.0f, 1.41421356237309505f};
#pragma unroll
    for (int a = 0; a < 3; a++) {
        float hs = (float)(strd * 8) * sr[a];
        float ws = (float)(strd * 8) * sr[2 - a];
        float a0 = __fadd_rn(y,  -0.5f * hs);
        float a1 = __fadd_rn(xx, -0.5f * ws);
        float a2 = __fadd_rn(y,   0.5f * hs);
        float a3 = __fadd_rn(xx,  0.5f * ws);
        float ah = __fadd_rn(a2, -a0);
        float aw = __fadd_rn(a3, -a1);
        float acy = __fadd_rn(a0, __fmul_rn(0.5f, ah));
        float acx = __fadd_rn(a1, __fmul_rn(0.5f, aw));
        float dy = acc[a * 4 + 0], dx = acc[a * 4 + 1];
        float dh = acc[a * 4 + 2], dw = acc[a * 4 + 3];
        float cy = __fadd_rn(__fmul_rn(dy, ah), acy);
        float cx = __fadd_rn(__fmul_rn(dx, aw), acx);
        float bh = __fmul_rn(expf(dh), ah);
        float bw = __fmul_rn(expf(dw), aw);
        float b0 = fminf(fmaxf(__fadd_rn(cy, -__fmul_rn(0.5f, bh)), 0.f), 1024.f);
        float b1 = fminf(fmaxf(__fadd_rn(cx, -__fmul_rn(0.5f, bw)), 0.f), 1024.f);
        float b2 = fminf(fmaxf(__fadd_rn(cy,  __fmul_rn(0.5f, bh)), 0.f), 1024.f);
        float b3 = fminf(fmaxf(__fadd_rn(cx,  __fmul_rn(0.5f, bw)), 0.f), 1024.f);

        float s0 = acc[12 + a * 2], s1 = acc[12 + a * 2 + 1];
        float m  = fmaxf(s0, s1);
        float e0 = expf(__fadd_rn(s0, -m));
        float e1 = expf(__fadd_rn(s1, -m));
        float fg = __fdiv_rn(e1, __fadd_rn(e0, e1));

        float hh  = __fadd_rn(b2, -b0);
        float ww2 = __fadd_rn(b3, -b1);
        float scv = (hh >= 16.f && ww2 >= 16.f) ? fg : NEGV;

        int aid = pix * 3 + a;
        g_boxes[aid]  = make_float4(b0, b1, b2, b3);
        g_scores[aid] = scv;
    }
}

// ---------------- exact top-6000 via 4-pass radix select ----------------
__device__ __forceinline__ unsigned int fkey(float f) {
    unsigned int u = __float_as_uint(f);
    return u ^ ((u & 0x80000000u) ? 0xFFFFFFFFu : 0x80000000u);
}

__global__ void topk_init() {
    int t = threadIdx.x;
    if (t < 256) g_hist[t] = 0;
    if (t == 0) { g_prefix = 0; g_above = 0; g_remain = PRE_NMS_N; g_ctr = 0; g_tiectr = 0; }
}

__global__ void topk_hist(int shift, unsigned int mask) {
    __shared__ unsigned int sh[256];
    if (threadIdx.x < 256) sh[threadIdx.x] = 0;
    __syncthreads();
    unsigned int pref = g_prefix;
    for (int i = blockIdx.x * blockDim.x + threadIdx.x; i < NANCH; i += gridDim.x * blockDim.x) {
        unsigned int k = fkey(g_scores[i]);
        if ((k & mask) == (pref & mask)) atomicAdd(&sh[(k >> shift) & 255u], 1u);
    }
    __syncthreads();
    if (threadIdx.x < 256 && sh[threadIdx.x]) atomicAdd(&g_hist[threadIdx.x], sh[threadIdx.x]);
}

__global__ void topk_select(int shift) {
    __shared__ unsigned int h[256];
    int t = threadIdx.x;
    h[t] = g_hist[t];
    __syncthreads();
    if (t == 0) {
        unsigned int remain = g_remain;
        unsigned int cum = 0;
        int b = 255;
        for (; b > 0; b--) {
            if (cum + h[b] >= remain) break;
            cum += h[b];
        }
        g_above  = g_above + cum;
        g_remain = remain - cum;
        g_prefix = g_prefix | ((unsigned int)b << shift);
    }
    __syncthreads();
    g_hist[t] = 0;
}

__global__ void topk_compact() {
    unsigned int kt = g_prefix;
    for (int i = blockIdx.x * blockDim.x + threadIdx.x; i < NANCH; i += gridDim.x * blockDim.x) {
        float s = g_scores[i];
        unsigned int k = fkey(s);
        if (k > kt) {
            int p = atomicAdd(&g_ctr, 1);
            g_tb[p] = g_boxes[i];
            g_ts[p] = s;
            g_ti[p] = i;
        } else if (k == kt) {
            int p = atomicAdd(&g_tiectr, 1);
            if (p < TIE_CAP) g_ties[p] = i;
        }
    }
}

__global__ void topk_ties() {
    int need = (int)g_remain;
    int base = (int)g_above;
    int M = g_tiectr;
    if (M > TIE_CAP) M = TIE_CAP;
    for (int i = threadIdx.x; i < M; i += blockDim.x) {
        int idx = g_ties[i];
        int rank = 0;
        for (int j = 0; j < M; j++) rank += (g_ties[j] < idx) ? 1 : 0;
        if (rank < need) {
            int p = base + rank;
            g_tb[p] = g_boxes[idx];
            g_ts[p] = g_scores[idx];
            g_ti[p] = idx;
        }
    }
}

// ---------------- sequential NMS: register-resident, packed u64 keys ----------
__global__ __launch_bounds__(1024) void nms_kernel(float* __restrict__ out) {
    __shared__ u64 rk[32];
    __shared__ int rp[32];
    __shared__ float4 curbox;
    __shared__ float cura;
    __shared__ int curpos, curvalid;

    const int t = threadIdx.x;
    float4 bx[6];
    float  ar[6];
    u64    key[6];

#pragma unroll
    for (int k = 0; k < 6; k++) {
        int i = k * 1024 + t;
        if (i < PRE_NMS_N) {
            float4 b = g_tb[i];
            bx[k] = b;
            ar[k] = __fmul_rn(__fadd_rn(b.z, -b.x), __fadd_rn(b.w, -b.y));
            key[k] = ((u64)fkey(g_ts[i]) << 32) | (u64)(unsigned)(~(unsigned)g_ti[i]);
        } else {
            bx[k] = make_float4(0.f, 0.f, 0.f, 0.f);
            ar[k] = 0.f;
            key[k] = 0ull;
        }
    }
    const unsigned vthr = fkey(NEGV * 0.5f);
    const u64 deadhi = ((u64)fkey(NEGV)) << 32;
    __syncthreads();

    for (int it = 0; it < POST_NMS_N; it++) {
        u64 bk = key[0];
        int bp = t;
#pragma unroll
        for (int k = 1; k < 6; k++) {
            if (key[k] > bk) { bk = key[k]; bp = k * 1024 + t; }
        }
#pragma unroll
        for (int d = 16; d > 0; d >>= 1) {
            u64 ok = __shfl_down_sync(0xffffffffu, bk, d);
            int op = __shfl_down_sync(0xffffffffu, bp, d);
            if (ok > bk) { bk = ok; bp = op; }
        }
        if ((t & 31) == 0) { rk[t >> 5] = bk; rp[t >> 5] = bp; }
        __syncthreads();
        if (t < 32) {
            bk = rk[t]; bp = rp[t];
#pragma unroll
            for (int d = 16; d > 0; d >>= 1) {
                u64 ok = __shfl_down_sync(0xffffffffu, bk, d);
                int op = __shfl_down_sync(0xffffffffu, bp, d);
                if (ok > bk) { bk = ok; bp = op; }
            }
            if (t == 0) {
                curpos = bp;
                int valid = ((unsigned)(bk >> 32) > vthr) ? 1 : 0;
                curvalid = valid;
                if (!valid) {
                    out[it * 4 + 0] = 0.f;
                    out[it * 4 + 1] = 0.f;
                    out[it * 4 + 2] = 0.f;
                    out[it * 4 + 3] = 0.f;
                }
            }
        }
        __syncthreads();
        if (curvalid && t == (curpos & 1023)) {
            int k = curpos >> 10;
            float4 b = bx[k];
            curbox = b;
            cura = ar[k];
            out[it * 4 + 0] = b.x;
            out[it * 4 + 1] = b.y;
            out[it * 4 + 2] = b.z;
            out[it * 4 + 3] = b.w;
            key[k] = deadhi | (key[k] & 0xFFFFFFFFull);
        }
        __syncthreads();
        if (curvalid) {
            float4 bb = curbox;
            float a1 = cura;
#pragma unroll
            for (int k = 0; k < 6; k++) {
                float4 c = bx[k];
                float ty = fmaxf(bb.x, c.x);
                float tx = fmaxf(bb.y, c.y);
                float by = fminf(bb.z, c.z);
                float bxx = fminf(bb.w, c.w);
                float inter = __fmul_rn(fmaxf(__fadd_rn(by, -ty), 0.f),
                                        fmaxf(__fadd_rn(bxx, -tx), 0.f));
                if (inter > 0.f) {
                    float iou = __fdiv_rn(inter,
                        fmaxf(__fadd_rn(__fadd_rn(a1, ar[k]), -inter), 1e-9f));
                    if (iou > 0.7f) key[k] = deadhi | (key[k] & 0xFFFFFFFFull);
                }
            }
        }
    }
}

// ---------------- host launcher ----------------
extern "C" void kernel_launch(void* const* d_in, const int* in_sizes, int n_in,
                              void* d_out, int out_size)
{
    (void)in_sizes; (void)n_in; (void)out_size;
    const float* p2 = (const float*)d_in[0];
    const float* p3 = (const float*)d_in[1];
    const float* p4 = (const float*)d_in[2];
    const float* p5 = (const float*)d_in[3];
    const float* p6 = (const float*)d_in[4];
    const float* conv_w  = (const float*)d_in[5];
    const float* conv_b  = (const float*)d_in[6];
    const float* loc_w   = (const float*)d_in[7];
    const float* loc_b   = (const float*)d_in[8];
    const float* score_w = (const float*)d_in[9];
    const float* score_b = (const float*)d_in[10];
    float* out = (float*)d_out;

    cudaFuncSetAttribute(w2_gemm_k, cudaFuncAttributeMaxDynamicSharedMemorySize, W2_SMEM);

    w0_wtrans<<<256, 256>>>(conv_w);                         // launch 0
    w1_xtrans<<<dim3(341, 64), 256>>>(p2, p3, p4, p5, p6);   // launch 1
    dummy_k<<<1, 32>>>();                                    // launch 2
    w2_gemm_k<<<dim3(341, 16), 256, W2_SMEM>>>();            // launch 3 <- ncu capture slot
    w3_otrans<<<dim3(341, 16), 256>>>(conv_b);

    heads_decode<<<682, 128>>>(loc_w, loc_b, score_w, score_b);

    topk_init<<<1, 256>>>();
    const int shifts[4] = {24, 16, 8, 0};
    const unsigned int masks[4] = {0x00000000u, 0xFF000000u, 0xFFFF0000u, 0xFFFFFF00u};
    for (int p = 0; p < 4; p++) {
        topk_hist<<<512, 256>>>(shifts[p], masks[p]);
        topk_select<<<1, 256>>>(shifts[p]);
    }
    topk_compact<<<512, 256>>>();
    topk_ties<<<1, 1024>>>();

    nms_kernel<<<1, 1024>>>(out);
}

// round 12
// speedup vs baseline: 1.0286x; 1.0286x over previous
#include <cuda_runtime.h>
#include <math.h>

#define HTOT 87296
#define NANCH 261888
#define PRE_NMS_N 6000
#define POST_NMS_N 300
#define NEGV -1000000000.0f
#define TIE_CAP 16384
#define STTOT 21824

typedef unsigned long long u64;
typedef unsigned int u32;

// ---------------- device scratch ----------------
static __device__ __align__(16) float g_h[(size_t)256 * HTOT];
static __device__ __align__(16) float g_V[(size_t)16 * 256 * STTOT];  // winograd V; reused in-place as M
static __device__ __align__(16) float g_U[(size_t)16 * 256 * 256];    // transformed weights (scalar, no dup)
#define g_M g_V   // safe alias: w2 block (stb,k) reads V[k][:,st-tile] fully before writing M[k][:,st-tile]
static __device__ float4 g_boxes[NANCH];
static __device__ float  g_scores[NANCH];
static __device__ float4 g_tb[PRE_NMS_N];
static __device__ float  g_ts[PRE_NMS_N];
static __device__ int    g_ti[PRE_NMS_N];
static __device__ unsigned int g_hist[256];
static __device__ unsigned int g_prefix, g_above, g_remain;
static __device__ int g_ctr, g_tiectr;
static __device__ int g_ties[TIE_CAP];

// ---------------- f32x2 / cp.async helpers ----------------
__device__ __forceinline__ void ffma2(u64& d, u64 a, u64 b) {
    asm("fma.rn.f32x2 %0, %1, %2, %0;" : "+l"(d) : "l"(a), "l"(b));
}
__device__ __forceinline__ u64 dup2(float v) {
    u64 r;
    asm("mov.b64 %0, {%1, %2};" : "=l"(r) : "f"(v), "f"(v));
    return r;
}
__device__ __forceinline__ void cpasync16(u32 saddr, const void* gptr) {
    asm volatile("cp.async.cg.shared.global [%0], [%1], 16;" :: "r"(saddr), "l"(gptr));
}
__device__ __forceinline__ void cp_commit() {
    asm volatile("cp.async.commit_group;");
}

__global__ void dummy_k() {}

// ---------------- W0: weight transform U = G w G^T (scalar layout) ------
__global__ __launch_bounds__(256) void w0_wtrans(const float* __restrict__ w) {
    int oc = blockIdx.x;
    int ic = threadIdx.x;
    const float* g = w + ((size_t)oc * 256 + ic) * 9;
    float g0 = g[0], g1 = g[1], g2 = g[2];
    float g3 = g[3], g4 = g[4], g5 = g[5];
    float g6 = g[6], g7 = g[7], g8 = g[8];

    float T[4][3];
    T[0][0] = g0; T[0][1] = g1; T[0][2] = g2;
    T[1][0] = 0.5f * (g0 + g3 + g6); T[1][1] = 0.5f * (g1 + g4 + g7); T[1][2] = 0.5f * (g2 + g5 + g8);
    T[2][0] = 0.5f * (g0 - g3 + g6); T[2][1] = 0.5f * (g1 - g4 + g7); T[2][2] = 0.5f * (g2 - g5 + g8);
    T[3][0] = g6; T[3][1] = g7; T[3][2] = g8;

#pragma unroll
    for (int r = 0; r < 4; r++) {
        float u0 = T[r][0];
        float u1 = 0.5f * (T[r][0] + T[r][1] + T[r][2]);
        float u2 = 0.5f * (T[r][0] - T[r][1] + T[r][2]);
        float u3 = T[r][2];
        float uv[4] = {u0, u1, u2, u3};
#pragma unroll
        for (int c = 0; c < 4; c++) {
            int k = r * 4 + c;
            g_U[((size_t)k * 256 + ic) * 256 + oc] = uv[c];
        }
    }
}

// ---------------- W1: input transform V = B^T d B (per-thread LDG) -------
__global__ __launch_bounds__(256) void w1_xtrans(
    const float* __restrict__ p2, const float* __restrict__ p3,
    const float* __restrict__ p4, const float* __restrict__ p5,
    const float* __restrict__ p6)
{
    int stb = blockIdx.x;          // 0..340
    int icg = blockIdx.y;          // 0..63
    int t = threadIdx.x;
    int stl = t & 63;
    int icl = t >> 6;
    int st0 = stb * 64;

    const float* x; int W, lsw, stoff;
    if (st0 < 16384)       { x = p2; W = 256; lsw = 7; stoff = 0; }
    else if (st0 < 20480)  { x = p3; W = 128; lsw = 6; stoff = 16384; }
    else if (st0 < 21504)  { x = p4; W = 64;  lsw = 5; stoff = 20480; }
    else if (st0 < 21760)  { x = p5; W = 32;  lsw = 4; stoff = 21504; }
    else                   { x = p6; W = 16;  lsw = 3; stoff = 21760; }
    int SW = W >> 1;

    int ic = icg * 4 + icl;
    int st = st0 + stl;
    int sidx = st - stoff;
    int sy = sidx >> lsw;
    int sx = sidx & (SW - 1);
    int py = 2 * sy - 1;
    int px = 2 * sx - 1;
    const float* xp = x + (size_t)ic * W * W;

    float d[4][4];
#pragma unroll
    for (int r = 0; r < 4; r++) {
        int yy = py + r;
        bool yok = (yy >= 0) && (yy < W);
#pragma unroll
        for (int c = 0; c < 4; c++) {
            int xx = px + c;
            d[r][c] = (yok && xx >= 0 && xx < W) ? xp[yy * W + xx] : 0.f;
        }
    }
    float e[4][4];
#pragma unroll
    for (int c = 0; c < 4; c++) {
        e[0][c] = d[0][c] - d[2][c];
        e[1][c] = d[1][c] + d[2][c];
        e[2][c] = d[2][c] - d[1][c];
        e[3][c] = d[1][c] - d[3][c];
    }
    float V[4][4];
#pragma unroll
    for (int r = 0; r < 4; r++) {
        V[r][0] = e[r][0] - e[r][2];
        V[r][1] = e[r][1] + e[r][2];
        V[r][2] = e[r][2] - e[r][1];
        V[r][3] = e[r][1] - e[r][3];
    }
    size_t base = (size_t)ic * STTOT + st;
#pragma unroll
    for (int r = 0; r < 4; r++)
#pragma unroll
        for (int c = 0; c < 4; c++)
            g_V[(size_t)(r * 4 + c) * 256 * STTOT + base] = V[r][c];
}

// ---------------- W2: pure GEMM per k, 3-buffer single-sync pipeline -----
// block = (stb, k): 256 oc x 64 st x 256 ic. thread = 8 oc x 8 st.
// buffer: V 16x64 (4KB) + U 16x256 scalar (16KB) = 5120 floats; 3 buffers.
#define W2_BUF 5120
#define W2_SMEM (3 * W2_BUF * 4)

__global__ __launch_bounds__(256, 2) void w2_gemm_k() {
    extern __shared__ __align__(16) float sm[];

    const int t   = threadIdx.x;
    const int stb = blockIdx.x;    // 0..340
    const int k   = blockIdx.y;    // 0..15
    const int st0 = stb * 64;
    const int thr_oc = t >> 3;     // 0..31
    const int thr_st = t & 7;      // 0..7

    u64 m[8][4];
#pragma unroll
    for (int o = 0; o < 8; o++)
#pragma unroll
        for (int s = 0; s < 4; s++) m[o][s] = 0ull;

    const float* Vbase = g_V + (size_t)k * 256 * STTOT + st0;
    const float* Ubase = g_U + (size_t)k * 256 * 256;

    // staging mapping
    const int vr = t >> 4;              // ic-local 0..15
    const int vcofs = (t & 15) * 4;     // col 0..60

    u32 smbase = (u32)__cvta_generic_to_shared(sm);

#define W2_PREFETCH(chunk, buf)                                                  \
    do {                                                                         \
        u32 bs_ = smbase + (buf) * (W2_BUF * 4);                                 \
        cpasync16(bs_ + (vr * 64 + vcofs) * 4,                                   \
                  Vbase + (size_t)((chunk) * 16 + vr) * STTOT + vcofs);          \
        const float* us_ = Ubase + (size_t)(chunk) * 16 * 256;                   \
        u32 ud_ = bs_ + 1024 * 4;                                                \
        _Pragma("unroll")                                                        \
        for (int j = 0; j < 4; j++)                                              \
            cpasync16(ud_ + (t + j * 256) * 16, us_ + (size_t)(t + j * 256) * 4);\
        cp_commit();                                                             \
    } while (0)

    W2_PREFETCH(0, 0);
    W2_PREFETCH(1, 1);

    for (int c = 0; c < 16; c++) {
        // chunk c committed when at most the chunk-(c+1) group is outstanding
        if (c < 15) asm volatile("cp.async.wait_group 1;");
        else        asm volatile("cp.async.wait_group 0;");
        __syncthreads();
        // prefetch into buffer (c+2)%3: last read at chunk c-1, ordered by the
        // sync above -> no second barrier needed per chunk
        if (c + 2 < 16) W2_PREFETCH(c + 2, (c + 2) % 3);

        const float* bs = sm + (c % 3) * W2_BUF;
        const float* Vc = bs;
        const float* Uc = bs + 1024;
#pragma unroll
        for (int ic = 0; ic < 16; ic++) {
            const ulonglong2* vp = (const ulonglong2*)(Vc + ic * 64 + thr_st * 8);
            ulonglong2 va = vp[0], vb = vp[1];
            u64 v[4] = {va.x, va.y, vb.x, vb.y};
            const float4* up = (const float4*)(Uc + ic * 256 + thr_oc * 8);
            float4 ua4 = up[0], ub4 = up[1];
            u64 u[8];
            u[0] = dup2(ua4.x); u[1] = dup2(ua4.y);
            u[2] = dup2(ua4.z); u[3] = dup2(ua4.w);
            u[4] = dup2(ub4.x); u[5] = dup2(ub4.y);
            u[6] = dup2(ub4.z); u[7] = dup2(ub4.w);
#pragma unroll
            for (int o = 0; o < 8; o++)
#pragma unroll
                for (int s = 0; s < 4; s++) ffma2(m[o][s], v[s], u[o]);
        }
    }

    // all V reads for this (k, st-tile) are done; in-place write M over V
    __syncthreads();
#pragma unroll
    for (int o = 0; o < 8; o++) {
        int oc = thr_oc * 8 + o;
        u64* mp = (u64*)(g_M + ((size_t)k * 256 + oc) * STTOT + st0 + thr_st * 8);
        ulonglong2 s0, s1;
        s0.x = m[o][0]; s0.y = m[o][1];
        s1.x = m[o][2]; s1.y = m[o][3];
        *(ulonglong2*)mp = s0;
        *(ulonglong2*)(mp + 2) = s1;
    }
}

// ---------------- W3: output transform A^T M A + bias + relu ----------------
__global__ __launch_bounds__(256) void w3_otrans(const float* __restrict__ bias) {
    const int stb = blockIdx.x;    // 0..340
    const int ocg = blockIdx.y;    // 0..15
    const int t = threadIdx.x;
    const int stl = t & 63;
    const int ocl = t >> 6;
    const int st0 = stb * 64;
    const int st  = st0 + stl;

    int W, lsw, stoff, pixoff;
    if (st0 < 16384)       { W = 256; lsw = 7; stoff = 0;     pixoff = 0; }
    else if (st0 < 20480)  { W = 128; lsw = 6; stoff = 16384; pixoff = 65536; }
    else if (st0 < 21504)  { W = 64;  lsw = 5; stoff = 20480; pixoff = 81920; }
    else if (st0 < 21760)  { W = 32;  lsw = 4; stoff = 21504; pixoff = 86016; }
    else                   { W = 16;  lsw = 3; stoff = 21760; pixoff = 87040; }
    int SW = W >> 1;

    int sidx = st - stoff;
    int sy = sidx >> lsw;
    int sx = sidx & (SW - 1);

#pragma unroll
    for (int o4 = 0; o4 < 4; o4++) {
        int oc = ocg * 16 + ocl * 4 + o4;
        const float* Mp = g_M + (size_t)oc * STTOT + st;
        float Mv[16];
#pragma unroll
        for (int kk = 0; kk < 16; kk++)
            Mv[kk] = Mp[(size_t)kk * 256 * STTOT];

        float e0[4], e1[4];
#pragma unroll
        for (int c = 0; c < 4; c++) {
            e0[c] = Mv[c] + Mv[4 + c] + Mv[8 + c];
            e1[c] = Mv[4 + c] - Mv[8 + c] - Mv[12 + c];
        }
        float o00 = e0[0] + e0[1] + e0[2];
        float o01 = e0[1] - e0[2] - e0[3];
        float o10 = e1[0] + e1[1] + e1[2];
        float o11 = e1[1] - e1[2] - e1[3];

        float bv = bias[oc];
        float* hp = g_h + (size_t)oc * HTOT + pixoff;
        float2 r0, r1;
        r0.x = fmaxf(o00 + bv, 0.f);
        r0.y = fmaxf(o01 + bv, 0.f);
        r1.x = fmaxf(o10 + bv, 0.f);
        r1.y = fmaxf(o11 + bv, 0.f);
        *(float2*)&hp[(2 * sy) * W + 2 * sx]     = r0;
        *(float2*)&hp[(2 * sy + 1) * W + 2 * sx] = r1;
    }
}

// ---------------- heads: 1x1 convs + softmax + decode + min-size ----------------
__global__ __launch_bounds__(128) void heads_decode(
    const float* __restrict__ lw, const float* __restrict__ lb,
    const float* __restrict__ sw, const float* __restrict__ sb)
{
    __shared__ float WL[12][256];
    __shared__ float WS[6][256];
    __shared__ float BL[12], BS[6];
    const int t = threadIdx.x;
    for (int i = t; i < 12 * 256; i += 128) WL[i >> 8][i & 255] = lw[i];
    for (int i = t; i < 6 * 256; i += 128)  WS[i >> 8][i & 255] = sw[i];
    if (t < 12) BL[t] = lb[t];
    if (t < 6)  BS[t] = sb[t];
    __syncthreads();

    const int pix = blockIdx.x * 128 + t;
    int lvl;
    if (pix < 65536) lvl = 0;
    else if (pix < 81920) lvl = 1;
    else if (pix < 86016) lvl = 2;
    else if (pix < 87040) lvl = 3;
    else lvl = 4;
    const int offs[5] = {0, 65536, 81920, 86016, 87040};
    const int lp   = pix - offs[lvl];
    const int lw2  = 8 - lvl;
    const int row  = lp >> lw2;
    const int col  = lp & ((1 << lw2) - 1);
    const int strd = 4 << lvl;

    float acc[18];
#pragma unroll
    for (int j = 0; j < 12; j++) acc[j] = BL[j];
#pragma unroll
    for (int j = 0; j < 6; j++)  acc[12 + j] = BS[j];

    const float* hp = g_h + pix;
#pragma unroll 4
    for (int ic = 0; ic < 256; ic++) {
        float v = hp[(size_t)ic * HTOT];
#pragma unroll
        for (int j = 0; j < 12; j++) acc[j] = fmaf(WL[j][ic], v, acc[j]);
#pragma unroll
        for (int j = 0; j < 6; j++)  acc[12 + j] = fmaf(WS[j][ic], v, acc[12 + j]);
    }

    const float y  = (float)(row * strd);
    const float xx = (float)(col * strd);
    const float sr[3] = {0.70710678118654752f, 1.0f, 1.41421356237309505f};
#pragma unroll
    for (int a = 0; a < 3; a++) {
        float hs = (float)(strd * 8) * sr[a];
        float ws = (float)(strd * 8) * sr[2 - a];
        float a0 = __fadd_rn(y,  -0.5f * hs);
        float a1 = __fadd_rn(xx, -0.5f * ws);
        float a2 = __fadd_rn(y,   0.5f * hs);
        float a3 = __fadd_rn(xx,  0.5f * ws);
        float ah = __fadd_rn(a2, -a0);
        float aw = __fadd_rn(a3, -a1);
        float acy = __fadd_rn(a0, __fmul_rn(0.5f, ah));
        float acx = __fadd_rn(a1, __fmul_rn(0.5f, aw));
        float dy = acc[a * 4 + 0], dx = acc[a * 4 + 1];
        float dh = acc[a * 4 + 2], dw = acc[a * 4 + 3];
        float cy = __fadd_rn(__fmul_rn(dy, ah), acy);
        float cx = __fadd_rn(__fmul_rn(dx, aw), acx);
        float bh = __fmul_rn(expf(dh), ah);
        float bw = __fmul_rn(expf(dw), aw);
        float b0 = fminf(fmaxf(__fadd_rn(cy, -__fmul_rn(0.5f, bh)), 0.f), 1024.f);
        float b1 = fminf(fmaxf(__fadd_rn(cx, -__fmul_rn(0.5f, bw)), 0.f), 1024.f);
        float b2 = fminf(fmaxf(__fadd_rn(cy,  __fmul_rn(0.5f, bh)), 0.f), 1024.f);
        float b3 = fminf(fmaxf(__fadd_rn(cx,  __fmul_rn(0.5f, bw)), 0.f), 1024.f);

        float s0 = acc[12 + a * 2], s1 = acc[12 + a * 2 + 1];
        float m  = fmaxf(s0, s1);
        float e0 = expf(__fadd_rn(s0, -m));
        float e1 = expf(__fadd_rn(s1, -m));
        float fg = __fdiv_rn(e1, __fadd_rn(e0, e1));

        float hh  = __fadd_rn(b2, -b0);
        float ww2 = __fadd_rn(b3, -b1);
        float scv = (hh >= 16.f && ww2 >= 16.f) ? fg : NEGV;

        int aid = pix * 3 + a;
        g_boxes[aid]  = make_float4(b0, b1, b2, b3);
        g_scores[aid] = scv;
    }
}

// ---------------- exact top-6000 via 4-pass radix select ----------------
__device__ __forceinline__ unsigned int fkey(float f) {
    unsigned int u = __float_as_uint(f);
    return u ^ ((u & 0x80000000u) ? 0xFFFFFFFFu : 0x80000000u);
}

__global__ void topk_init() {
    int t = threadIdx.x;
    if (t < 256) g_hist[t] = 0;
    if (t == 0) { g_prefix = 0; g_above = 0; g_remain = PRE_NMS_N; g_ctr = 0; g_tiectr = 0; }
}

__global__ void topk_hist(int shift, unsigned int mask) {
    __shared__ unsigned int sh[256];
    if (threadIdx.x < 256) sh[threadIdx.x] = 0;
    __syncthreads();
    unsigned int pref = g_prefix;
    for (int i = blockIdx.x * blockDim.x + threadIdx.x; i < NANCH; i += gridDim.x * blockDim.x) {
        unsigned int k = fkey(g_scores[i]);
        if ((k & mask) == (pref & mask)) atomicAdd(&sh[(k >> shift) & 255u], 1u);
    }
    __syncthreads();
    if (threadIdx.x < 256 && sh[threadIdx.x]) atomicAdd(&g_hist[threadIdx.x], sh[threadIdx.x]);
}

__global__ void topk_select(int shift) {
    __shared__ unsigned int h[256];
    int t = threadIdx.x;
    h[t] = g_hist[t];
    __syncthreads();
    if (t == 0) {
        unsigned int remain = g_remain;
        unsigned int cum = 0;
        int b = 255;
        for (; b > 0; b--) {
            if (cum + h[b] >= remain) break;
            cum += h[b];
        }
        g_above  = g_above + cum;
        g_remain = remain - cum;
        g_prefix = g_prefix | ((unsigned int)b << shift);
    }
    __syncthreads();
    g_hist[t] = 0;
}

__global__ void topk_compact() {
    unsigned int kt = g_prefix;
    for (int i = blockIdx.x * blockDim.x + threadIdx.x; i < NANCH; i += gridDim.x * blockDim.x) {
        float s = g_scores[i];
        unsigned int k = fkey(s);
        if (k > kt) {
            int p = atomicAdd(&g_ctr, 1);
            g_tb[p] = g_boxes[i];
            g_ts[p] = s;
            g_ti[p] = i;
        } else if (k == kt) {
            int p = atomicAdd(&g_tiectr, 1);
            if (p < TIE_CAP) g_ties[p] = i;
        }
    }
}

__global__ void topk_ties() {
    int need = (int)g_remain;
    int base = (int)g_above;
    int M = g_tiectr;
    if (M > TIE_CAP) M = TIE_CAP;
    for (int i = threadIdx.x; i < M; i += blockDim.x) {
        int idx = g_ties[i];
        int rank = 0;
        for (int j = 0; j < M; j++) rank += (g_ties[j] < idx) ? 1 : 0;
        if (rank < need) {
            int p = base + rank;
            g_tb[p] = g_boxes[idx];
            g_ts[p] = g_scores[idx];
            g_ti[p] = idx;
        }
    }
}

// ---------------- sequential NMS: register-resident, packed u64 keys ----------
__global__ __launch_bounds__(1024) void nms_kernel(float* __restrict__ out) {
    __shared__ u64 rk[32];
    __shared__ int rp[32];
    __shared__ float4 curbox;
    __shared__ float cura;
    __shared__ int curpos, curvalid;

    const int t = threadIdx.x;
    float4 bx[6];
    float  ar[6];
    u64    key[6];

#pragma unroll
    for (int k = 0; k < 6; k++) {
        int i = k * 1024 + t;
        if (i < PRE_NMS_N) {
            float4 b = g_tb[i];
            bx[k] = b;
            ar[k] = __fmul_rn(__fadd_rn(b.z, -b.x), __fadd_rn(b.w, -b.y));
            key[k] = ((u64)fkey(g_ts[i]) << 32) | (u64)(unsigned)(~(unsigned)g_ti[i]);
        } else {
            bx[k] = make_float4(0.f, 0.f, 0.f, 0.f);
            ar[k] = 0.f;
            key[k] = 0ull;
        }
    }
    const unsigned vthr = fkey(NEGV * 0.5f);
    const u64 deadhi = ((u64)fkey(NEGV)) << 32;
    __syncthreads();

    for (int it = 0; it < POST_NMS_N; it++) {
        u64 bk = key[0];
        int bp = t;
#pragma unroll
        for (int k = 1; k < 6; k++) {
            if (key[k] > bk) { bk = key[k]; bp = k * 1024 + t; }
        }
#pragma unroll
        for (int d = 16; d > 0; d >>= 1) {
            u64 ok = __shfl_down_sync(0xffffffffu, bk, d);
            int op = __shfl_down_sync(0xffffffffu, bp, d);
            if (ok > bk) { bk = ok; bp = op; }
        }
        if ((t & 31) == 0) { rk[t >> 5] = bk; rp[t >> 5] = bp; }
        __syncthreads();
        if (t < 32) {
            bk = rk[t]; bp = rp[t];
#pragma unroll
            for (int d = 16; d > 0; d >>= 1) {
                u64 ok = __shfl_down_sync(0xffffffffu, bk, d);
                int op = __shfl_down_sync(0xffffffffu, bp, d);
                if (ok > bk) { bk = ok; bp = op; }
            }
            if (t == 0) {
                curpos = bp;
                int valid = ((unsigned)(bk >> 32) > vthr) ? 1 : 0;
                curvalid = valid;
                if (!valid) {
                    out[it * 4 + 0] = 0.f;
                    out[it * 4 + 1] = 0.f;
                    out[it * 4 + 2] = 0.f;
                    out[it * 4 + 3] = 0.f;
                }
            }
        }
        __syncthreads();
        if (curvalid && t == (curpos & 1023)) {
            int k = curpos >> 10;
            float4 b = bx[k];
            curbox = b;
            cura = ar[k];
            out[it * 4 + 0] = b.x;
            out[it * 4 + 1] = b.y;
            out[it * 4 + 2] = b.z;
            out[it * 4 + 3] = b.w;
            key[k] = deadhi | (key[k] & 0xFFFFFFFFull);
        }
        __syncthreads();
        if (curvalid) {
            float4 bb = curbox;
            float a1 = cura;
#pragma unroll
            for (int k = 0; k < 6; k++) {
                float4 c = bx[k];
                float ty = fmaxf(bb.x, c.x);
                float tx = fmaxf(bb.y, c.y);
                float by = fminf(bb.z, c.z);
                float bxx = fminf(bb.w, c.w);
                float inter = __fmul_rn(fmaxf(__fadd_rn(by, -ty), 0.f),
                                        fmaxf(__fadd_rn(bxx, -tx), 0.f));
                if (inter > 0.f) {
                    float iou = __fdiv_rn(inter,
                        fmaxf(__fadd_rn(__fadd_rn(a1, ar[k]), -inter), 1e-9f));
                    if (iou > 0.7f) key[k] = deadhi | (key[k] & 0xFFFFFFFFull);
                }
            }
        }
    }
}

// ---------------- host launcher ----------------
extern "C" void kernel_launch(void* const* d_in, const int* in_sizes, int n_in,
                              void* d_out, int out_size)
{
    (void)in_sizes; (void)n_in; (void)out_size;
    const float* p2 = (const float*)d_in[0];
    const float* p3 = (const float*)d_in[1];
    const float* p4 = (const float*)d_in[2];
    const float* p5 = (const float*)d_in[3];
    const float* p6 = (const float*)d_in[4];
    const float* conv_w  = (const float*)d_in[5];
    const float* conv_b  = (const float*)d_in[6];
    const float* loc_w   = (const float*)d_in[7];
    const float* loc_b   = (const float*)d_in[8];
    const float* score_w = (const float*)d_in[9];
    const float* score_b = (const float*)d_in[10];
    float* out = (float*)d_out;

    cudaFuncSetAttribute(w2_gemm_k, cudaFuncAttributeMaxDynamicSharedMemorySize, W2_SMEM);

    w0_wtrans<<<256, 256>>>(conv_w);                         // launch 0
    w1_xtrans<<<dim3(341, 64), 256>>>(p2, p3, p4, p5, p6);   // launch 1
    dummy_k<<<1, 32>>>();                                    // launch 2
    w2_gemm_k<<<dim3(341, 16), 256, W2_SMEM>>>();            // launch 3 <- ncu capture slot
    w3_otrans<<<dim3(341, 16), 256>>>(conv_b);

    heads_decode<<<682, 128>>>(loc_w, loc_b, score_w, score_b);

    topk_init<<<1, 256>>>();
    const int shifts[4] = {24, 16, 8, 0};
    const unsigned int masks[4] = {0x00000000u, 0xFF000000u, 0xFFFF0000u, 0xFFFFFF00u};
    for (int p = 0; p < 4; p++) {
        topk_hist<<<512, 256>>>(shifts[p], masks[p]);
        topk_select<<<1, 256>>>(shifts[p]);
    }
    topk_compact<<<512, 256>>>();
    topk_ties<<<1, 1024>>>();

    nms_kernel<<<1, 1024>>>(out);
}

// round 13
// speedup vs baseline: 1.0514x; 1.0222x over previous
#include <cuda_runtime.h>
#include <math.h>

#define HTOT 87296
#define NANCH 261888
#define PRE_NMS_N 6000
#define POST_NMS_N 300
#define NEGV -1000000000.0f
#define TIE_CAP 16384
#define STTOT 21824

typedef unsigned long long u64;
typedef unsigned int u32;

// ---------------- device scratch ----------------
static __device__ __align__(16) float g_h[(size_t)256 * HTOT];
static __device__ __align__(16) float g_V[(size_t)16 * 256 * STTOT];  // winograd V; reused in-place as M
static __device__ __align__(16) float g_U[(size_t)16 * 256 * 256];    // transformed weights (scalar, no dup)
#define g_M g_V   // safe alias: w2 block (stb,k) reads V[k][:,st-tile] fully before writing M[k][:,st-tile]
static __device__ float4 g_boxes[NANCH];
static __device__ float  g_scores[NANCH];
static __device__ float4 g_tb[PRE_NMS_N];
static __device__ float  g_ts[PRE_NMS_N];
static __device__ int    g_ti[PRE_NMS_N];
static __device__ unsigned int g_hist[256];
static __device__ unsigned int g_prefix, g_above, g_remain;
static __device__ int g_ctr, g_tiectr;
static __device__ int g_ties[TIE_CAP];

// ---------------- f32x2 / cp.async helpers ----------------
__device__ __forceinline__ void ffma2(u64& d, u64 a, u64 b) {
    asm("fma.rn.f32x2 %0, %1, %2, %0;" : "+l"(d) : "l"(a), "l"(b));
}
__device__ __forceinline__ u64 dup2(float v) {
    u64 r;
    asm("mov.b64 %0, {%1, %2};" : "=l"(r) : "f"(v), "f"(v));
    return r;
}
__device__ __forceinline__ void cpasync16(u32 saddr, const void* gptr) {
    asm volatile("cp.async.cg.shared.global [%0], [%1], 16;" :: "r"(saddr), "l"(gptr));
}
__device__ __forceinline__ void cp_commit() {
    asm volatile("cp.async.commit_group;");
}

__global__ void dummy_k() {}

// ---------------- W0: weight transform U = G w G^T (scalar layout) ------
__global__ __launch_bounds__(256) void w0_wtrans(const float* __restrict__ w) {
    int oc = blockIdx.x;
    int ic = threadIdx.x;
    const float* g = w + ((size_t)oc * 256 + ic) * 9;
    float g0 = g[0], g1 = g[1], g2 = g[2];
    float g3 = g[3], g4 = g[4], g5 = g[5];
    float g6 = g[6], g7 = g[7], g8 = g[8];

    float T[4][3];
    T[0][0] = g0; T[0][1] = g1; T[0][2] = g2;
    T[1][0] = 0.5f * (g0 + g3 + g6); T[1][1] = 0.5f * (g1 + g4 + g7); T[1][2] = 0.5f * (g2 + g5 + g8);
    T[2][0] = 0.5f * (g0 - g3 + g6); T[2][1] = 0.5f * (g1 - g4 + g7); T[2][2] = 0.5f * (g2 - g5 + g8);
    T[3][0] = g6; T[3][1] = g7; T[3][2] = g8;

#pragma unroll
    for (int r = 0; r < 4; r++) {
        float u0 = T[r][0];
        float u1 = 0.5f * (T[r][0] + T[r][1] + T[r][2]);
        float u2 = 0.5f * (T[r][0] - T[r][1] + T[r][2]);
        float u3 = T[r][2];
        float uv[4] = {u0, u1, u2, u3};
#pragma unroll
        for (int c = 0; c < 4; c++) {
            int k = r * 4 + c;
            g_U[((size_t)k * 256 + ic) * 256 + oc] = uv[c];
        }
    }
}

// ---------------- W1: input transform V = B^T d B (per-thread LDG) -------
__global__ __launch_bounds__(256) void w1_xtrans(
    const float* __restrict__ p2, const float* __restrict__ p3,
    const float* __restrict__ p4, const float* __restrict__ p5,
    const float* __restrict__ p6)
{
    int stb = blockIdx.x;          // 0..340
    int icg = blockIdx.y;          // 0..63
    int t = threadIdx.x;
    int stl = t & 63;
    int icl = t >> 6;
    int st0 = stb * 64;

    const float* x; int W, lsw, stoff;
    if (st0 < 16384)       { x = p2; W = 256; lsw = 7; stoff = 0; }
    else if (st0 < 20480)  { x = p3; W = 128; lsw = 6; stoff = 16384; }
    else if (st0 < 21504)  { x = p4; W = 64;  lsw = 5; stoff = 20480; }
    else if (st0 < 21760)  { x = p5; W = 32;  lsw = 4; stoff = 21504; }
    else                   { x = p6; W = 16;  lsw = 3; stoff = 21760; }
    int SW = W >> 1;

    int ic = icg * 4 + icl;
    int st = st0 + stl;
    int sidx = st - stoff;
    int sy = sidx >> lsw;
    int sx = sidx & (SW - 1);
    int py = 2 * sy - 1;
    int px = 2 * sx - 1;
    const float* xp = x + (size_t)ic * W * W;

    float d[4][4];
#pragma unroll
    for (int r = 0; r < 4; r++) {
        int yy = py + r;
        bool yok = (yy >= 0) && (yy < W);
#pragma unroll
        for (int c = 0; c < 4; c++) {
            int xx = px + c;
            d[r][c] = (yok && xx >= 0 && xx < W) ? xp[yy * W + xx] : 0.f;
        }
    }
    float e[4][4];
#pragma unroll
    for (int c = 0; c < 4; c++) {
        e[0][c] = d[0][c] - d[2][c];
        e[1][c] = d[1][c] + d[2][c];
        e[2][c] = d[2][c] - d[1][c];
        e[3][c] = d[1][c] - d[3][c];
    }
    float V[4][4];
#pragma unroll
    for (int r = 0; r < 4; r++) {
        V[r][0] = e[r][0] - e[r][2];
        V[r][1] = e[r][1] + e[r][2];
        V[r][2] = e[r][2] - e[r][1];
        V[r][3] = e[r][1] - e[r][3];
    }
    size_t base = (size_t)ic * STTOT + st;
#pragma unroll
    for (int r = 0; r < 4; r++)
#pragma unroll
        for (int c = 0; c < 4; c++)
            g_V[(size_t)(r * 4 + c) * 256 * STTOT + base] = V[r][c];
}

// ---------------- W2: pure GEMM per k, double-buffered cp.async ----------
// block = (stb, k): 256 oc x 64 st x 256 ic. thread = 8 oc x 8 st.
// buffer: V 16x64 (4KB) + U 16x256 scalar (16KB) = 5120 floats; 2 buffers.
#define W2_BUF 5120
#define W2_SMEM (2 * W2_BUF * 4)

__global__ __launch_bounds__(256, 2) void w2_gemm_k() {
    extern __shared__ __align__(16) float sm[];

    const int t   = threadIdx.x;
    const int stb = blockIdx.x;    // 0..340
    const int k   = blockIdx.y;    // 0..15
    const int st0 = stb * 64;
    const int thr_oc = t >> 3;     // 0..31
    const int thr_st = t & 7;      // 0..7

    u64 m[8][4];
#pragma unroll
    for (int o = 0; o < 8; o++)
#pragma unroll
        for (int s = 0; s < 4; s++) m[o][s] = 0ull;

    const float* Vbase = g_V + (size_t)k * 256 * STTOT + st0;
    const float* Ubase = g_U + (size_t)k * 256 * 256;

    // staging mapping
    const int vr = t >> 4;              // ic-local 0..15
    const int vcofs = (t & 15) * 4;     // col 0..60

    u32 smbase = (u32)__cvta_generic_to_shared(sm);

#define W2_PREFETCH(chunk, buf)                                                  \
    do {                                                                         \
        u32 bs_ = smbase + (buf) * (W2_BUF * 4);                                 \
        cpasync16(bs_ + (vr * 64 + vcofs) * 4,                                   \
                  Vbase + (size_t)((chunk) * 16 + vr) * STTOT + vcofs);          \
        const float* us_ = Ubase + (size_t)(chunk) * 16 * 256;                   \
        u32 ud_ = bs_ + 1024 * 4;                                                \
        _Pragma("unroll")                                                        \
        for (int j = 0; j < 4; j++)                                              \
            cpasync16(ud_ + (t + j * 256) * 16, us_ + (size_t)(t + j * 256) * 4);\
        cp_commit();                                                             \
    } while (0)

    W2_PREFETCH(0, 0);
    W2_PREFETCH(1, 1);

    for (int c = 0; c < 16; c++) {
        if (c < 15) asm volatile("cp.async.wait_group 1;");
        else        asm volatile("cp.async.wait_group 0;");
        __syncthreads();

        const float* bs = sm + (c & 1) * W2_BUF;
        const float* Vc = bs;
        const float* Uc = bs + 1024;
#pragma unroll
        for (int ic = 0; ic < 16; ic++) {
            const ulonglong2* vp = (const ulonglong2*)(Vc + ic * 64 + thr_st * 8);
            ulonglong2 va = vp[0], vb = vp[1];
            u64 v[4] = {va.x, va.y, vb.x, vb.y};
            const float4* up = (const float4*)(Uc + ic * 256 + thr_oc * 8);
            float4 ua4 = up[0], ub4 = up[1];
            u64 u[8];
            u[0] = dup2(ua4.x); u[1] = dup2(ua4.y);
            u[2] = dup2(ua4.z); u[3] = dup2(ua4.w);
            u[4] = dup2(ub4.x); u[5] = dup2(ub4.y);
            u[6] = dup2(ub4.z); u[7] = dup2(ub4.w);
#pragma unroll
            for (int o = 0; o < 8; o++)
#pragma unroll
                for (int s = 0; s < 4; s++) ffma2(m[o][s], v[s], u[o]);
        }
        __syncthreads();
        if (c + 2 < 16) W2_PREFETCH(c + 2, c & 1);
    }

    // all V reads for this (k, st-tile) are done; in-place write M over V
#pragma unroll
    for (int o = 0; o < 8; o++) {
        int oc = thr_oc * 8 + o;
        u64* mp = (u64*)(g_M + ((size_t)k * 256 + oc) * STTOT + st0 + thr_st * 8);
        ulonglong2 s0, s1;
        s0.x = m[o][0]; s0.y = m[o][1];
        s1.x = m[o][2]; s1.y = m[o][3];
        *(ulonglong2*)mp = s0;
        *(ulonglong2*)(mp + 2) = s1;
    }
}

// ---------------- W3: output transform A^T M A + bias + relu ----------------
__global__ __launch_bounds__(256) void w3_otrans(const float* __restrict__ bias) {
    const int stb = blockIdx.x;    // 0..340
    const int ocg = blockIdx.y;    // 0..15
    const int t = threadIdx.x;
    const int stl = t & 63;
    const int ocl = t >> 6;
    const int st0 = stb * 64;
    const int st  = st0 + stl;

    int W, lsw, stoff, pixoff;
    if (st0 < 16384)       { W = 256; lsw = 7; stoff = 0;     pixoff = 0; }
    else if (st0 < 20480)  { W = 128; lsw = 6; stoff = 16384; pixoff = 65536; }
    else if (st0 < 21504)  { W = 64;  lsw = 5; stoff = 20480; pixoff = 81920; }
    else if (st0 < 21760)  { W = 32;  lsw = 4; stoff = 21504; pixoff = 86016; }
    else                   { W = 16;  lsw = 3; stoff = 21760; pixoff = 87040; }
    int SW = W >> 1;

    int sidx = st - stoff;
    int sy = sidx >> lsw;
    int sx = sidx & (SW - 1);

#pragma unroll
    for (int o4 = 0; o4 < 4; o4++) {
        int oc = ocg * 16 + ocl * 4 + o4;
        const float* Mp = g_M + (size_t)oc * STTOT + st;
        float Mv[16];
#pragma unroll
        for (int kk = 0; kk < 16; kk++)
            Mv[kk] = Mp[(size_t)kk * 256 * STTOT];

        float e0[4], e1[4];
#pragma unroll
        for (int c = 0; c < 4; c++) {
            e0[c] = Mv[c] + Mv[4 + c] + Mv[8 + c];
            e1[c] = Mv[4 + c] - Mv[8 + c] - Mv[12 + c];
        }
        float o00 = e0[0] + e0[1] + e0[2];
        float o01 = e0[1] - e0[2] - e0[3];
        float o10 = e1[0] + e1[1] + e1[2];
        float o11 = e1[1] - e1[2] - e1[3];

        float bv = bias[oc];
        float* hp = g_h + (size_t)oc * HTOT + pixoff;
        float2 r0, r1;
        r0.x = fmaxf(o00 + bv, 0.f);
        r0.y = fmaxf(o01 + bv, 0.f);
        r1.x = fmaxf(o10 + bv, 0.f);
        r1.y = fmaxf(o11 + bv, 0.f);
        *(float2*)&hp[(2 * sy) * W + 2 * sx]     = r0;
        *(float2*)&hp[(2 * sy + 1) * W + 2 * sx] = r1;
    }
}

// ---------------- heads: 1x1 convs + softmax + decode, 2 px/thread -------
__global__ __launch_bounds__(128) void heads_decode(
    const float* __restrict__ lw, const float* __restrict__ lb,
    const float* __restrict__ sw, const float* __restrict__ sb)
{
    __shared__ float WL[12][256];
    __shared__ float WS[6][256];
    __shared__ float BL[12], BS[6];
    const int t = threadIdx.x;
    for (int i = t; i < 12 * 256; i += 128) WL[i >> 8][i & 255] = lw[i];
    for (int i = t; i < 6 * 256; i += 128)  WS[i >> 8][i & 255] = sw[i];
    if (t < 12) BL[t] = lb[t];
    if (t < 6)  BS[t] = sb[t];
    __syncthreads();

    const int pix0 = (blockIdx.x * 128 + t) * 2;   // even; both pixels same level
    int lvl;
    if (pix0 < 65536) lvl = 0;
    else if (pix0 < 81920) lvl = 1;
    else if (pix0 < 86016) lvl = 2;
    else if (pix0 < 87040) lvl = 3;
    else lvl = 4;
    const int offs[5] = {0, 65536, 81920, 86016, 87040};
    const int lp   = pix0 - offs[lvl];
    const int lw2  = 8 - lvl;
    const int row  = lp >> lw2;
    const int col0 = lp & ((1 << lw2) - 1);
    const int strd = 4 << lvl;

    float acc[2][18];
#pragma unroll
    for (int p = 0; p < 2; p++) {
#pragma unroll
        for (int j = 0; j < 12; j++) acc[p][j] = BL[j];
#pragma unroll
        for (int j = 0; j < 6; j++)  acc[p][12 + j] = BS[j];
    }

    const float* hp = g_h + pix0;
#pragma unroll 4
    for (int ic = 0; ic < 256; ic++) {
        float2 v = *(const float2*)(hp + (size_t)ic * HTOT);
#pragma unroll
        for (int j = 0; j < 12; j++) {
            float wv = WL[j][ic];
            acc[0][j] = fmaf(wv, v.x, acc[0][j]);
            acc[1][j] = fmaf(wv, v.y, acc[1][j]);
        }
#pragma unroll
        for (int j = 0; j < 6; j++) {
            float wv = WS[j][ic];
            acc[0][12 + j] = fmaf(wv, v.x, acc[0][12 + j]);
            acc[1][12 + j] = fmaf(wv, v.y, acc[1][12 + j]);
        }
    }

    const float sr[3] = {0.70710678118654752f, 1.0f, 1.41421356237309505f};
#pragma unroll
    for (int p = 0; p < 2; p++) {
        const int pix = pix0 + p;
        const float y  = (float)(row * strd);
        const float xx = (float)((col0 + p) * strd);
#pragma unroll
        for (int a = 0; a < 3; a++) {
            float hs = (float)(strd * 8) * sr[a];
            float ws = (float)(strd * 8) * sr[2 - a];
            float a0 = __fadd_rn(y,  -0.5f * hs);
            float a1 = __fadd_rn(xx, -0.5f * ws);
            float a2 = __fadd_rn(y,   0.5f * hs);
            float a3 = __fadd_rn(xx,  0.5f * ws);
            float ah = __fadd_rn(a2, -a0);
            float aw = __fadd_rn(a3, -a1);
            float acy = __fadd_rn(a0, __fmul_rn(0.5f, ah));
            float acx = __fadd_rn(a1, __fmul_rn(0.5f, aw));
            float dy = acc[p][a * 4 + 0], dx = acc[p][a * 4 + 1];
            float dh = acc[p][a * 4 + 2], dw = acc[p][a * 4 + 3];
            float cy = __fadd_rn(__fmul_rn(dy, ah), acy);
            float cx = __fadd_rn(__fmul_rn(dx, aw), acx);
            float bh = __fmul_rn(expf(dh), ah);
            float bw = __fmul_rn(expf(dw), aw);
            float b0 = fminf(fmaxf(__fadd_rn(cy, -__fmul_rn(0.5f, bh)), 0.f), 1024.f);
            float b1 = fminf(fmaxf(__fadd_rn(cx, -__fmul_rn(0.5f, bw)), 0.f), 1024.f);
            float b2 = fminf(fmaxf(__fadd_rn(cy,  __fmul_rn(0.5f, bh)), 0.f), 1024.f);
            float b3 = fminf(fmaxf(__fadd_rn(cx,  __fmul_rn(0.5f, bw)), 0.f), 1024.f);

            float s0 = acc[p][12 + a * 2], s1 = acc[p][12 + a * 2 + 1];
            float mm = fmaxf(s0, s1);
            float e0 = expf(__fadd_rn(s0, -mm));
            float e1 = expf(__fadd_rn(s1, -mm));
            float fg = __fdiv_rn(e1, __fadd_rn(e0, e1));

            float hh  = __fadd_rn(b2, -b0);
            float ww2 = __fadd_rn(b3, -b1);
            float scv = (hh >= 16.f && ww2 >= 16.f) ? fg : NEGV;

            int aid = pix * 3 + a;
            g_boxes[aid]  = make_float4(b0, b1, b2, b3);
            g_scores[aid] = scv;
        }
    }
}

// ---------------- exact top-6000 via 4-pass radix select ----------------
__device__ __forceinline__ unsigned int fkey(float f) {
    unsigned int u = __float_as_uint(f);
    return u ^ ((u & 0x80000000u) ? 0xFFFFFFFFu : 0x80000000u);
}

__global__ void topk_init() {
    int t = threadIdx.x;
    if (t < 256) g_hist[t] = 0;
    if (t == 0) { g_prefix = 0; g_above = 0; g_remain = PRE_NMS_N; g_ctr = 0; g_tiectr = 0; }
}

__global__ void topk_hist(int shift, unsigned int mask) {
    __shared__ unsigned int sh[256];
    if (threadIdx.x < 256) sh[threadIdx.x] = 0;
    __syncthreads();
    unsigned int pref = g_prefix;
    for (int i = blockIdx.x * blockDim.x + threadIdx.x; i < NANCH; i += gridDim.x * blockDim.x) {
        unsigned int k = fkey(g_scores[i]);
        if ((k & mask) == (pref & mask)) atomicAdd(&sh[(k >> shift) & 255u], 1u);
    }
    __syncthreads();
    if (threadIdx.x < 256 && sh[threadIdx.x]) atomicAdd(&g_hist[threadIdx.x], sh[threadIdx.x]);
}

__global__ void topk_select(int shift) {
    __shared__ unsigned int h[256];
    int t = threadIdx.x;
    h[t] = g_hist[t];
    __syncthreads();
    if (t == 0) {
        unsigned int remain = g_remain;
        unsigned int cum = 0;
        int b = 255;
        for (; b > 0; b--) {
            if (cum + h[b] >= remain) break;
            cum += h[b];
        }
        g_above  = g_above + cum;
        g_remain = remain - cum;
        g_prefix = g_prefix | ((unsigned int)b << shift);
    }
    __syncthreads();
    g_hist[t] = 0;
}

__global__ void topk_compact() {
    unsigned int kt = g_prefix;
    for (int i = blockIdx.x * blockDim.x + threadIdx.x; i < NANCH; i += gridDim.x * blockDim.x) {
        float s = g_scores[i];
        unsigned int k = fkey(s);
        if (k > kt) {
            int p = atomicAdd(&g_ctr, 1);
            g_tb[p] = g_boxes[i];
            g_ts[p] = s;
            g_ti[p] = i;
        } else if (k == kt) {
            int p = atomicAdd(&g_tiectr, 1);
            if (p < TIE_CAP) g_ties[p] = i;
        }
    }
}

__global__ void topk_ties() {
    int need = (int)g_remain;
    int base = (int)g_above;
    int M = g_tiectr;
    if (M > TIE_CAP) M = TIE_CAP;
    for (int i = threadIdx.x; i < M; i += blockDim.x) {
        int idx = g_ties[i];
        int rank = 0;
        for (int j = 0; j < M; j++) rank += (g_ties[j] < idx) ? 1 : 0;
        if (rank < need) {
            int p = base + rank;
            g_tb[p] = g_boxes[idx];
            g_ts[p] = g_scores[idx];
            g_ti[p] = idx;
        }
    }
}

// ---------------- sequential NMS: fused suppress+argmax, 2 barriers/iter --
#define NMS_SMEM (PRE_NMS_N * (sizeof(float4) + sizeof(float)))

__global__ __launch_bounds__(1024) void nms_kernel(float* __restrict__ out) {
    extern __shared__ char nsm[];
    float4* B = (float4*)nsm;
    float*  A = (float*)(B + PRE_NMS_N);
    __shared__ u64 rk[32];
    __shared__ int rp[32];
    __shared__ float4 curbox;
    __shared__ float cura;
    __shared__ int curpos, curvalid;

    const int t = threadIdx.x;
    float4 bx[6];
    float  ar[6];
    u64    key[6];

#pragma unroll
    for (int k = 0; k < 6; k++) {
        int i = k * 1024 + t;
        if (i < PRE_NMS_N) {
            float4 b = g_tb[i];
            float a = __fmul_rn(__fadd_rn(b.z, -b.x), __fadd_rn(b.w, -b.y));
            bx[k] = b;
            ar[k] = a;
            key[k] = ((u64)fkey(g_ts[i]) << 32) | (u64)(unsigned)(~(unsigned)g_ti[i]);
            B[i] = b;
            A[i] = a;
        } else {
            bx[k] = make_float4(0.f, 0.f, 0.f, 0.f);
            ar[k] = 0.f;
            key[k] = 0ull;
        }
    }
    const unsigned vthr = fkey(NEGV * 0.5f);
    const u64 deadhi = ((u64)fkey(NEGV)) << 32;

    // initial local candidate
    u64 lbk = key[0];
    int lbp = t;
#pragma unroll
    for (int k = 1; k < 6; k++)
        if (key[k] > lbk) { lbk = key[k]; lbp = k * 1024 + t; }
    __syncthreads();

    for (int it = 0; it < POST_NMS_N; it++) {
        u64 bk = lbk;
        int bp = lbp;
#pragma unroll
        for (int d = 16; d > 0; d >>= 1) {
            u64 ok = __shfl_down_sync(0xffffffffu, bk, d);
            int op = __shfl_down_sync(0xffffffffu, bp, d);
            if (ok > bk) { bk = ok; bp = op; }
        }
        if ((t & 31) == 0) { rk[t >> 5] = bk; rp[t >> 5] = bp; }
        __syncthreads();
        if (t < 32) {
            bk = rk[t]; bp = rp[t];
#pragma unroll
            for (int d = 16; d > 0; d >>= 1) {
                u64 ok = __shfl_down_sync(0xffffffffu, bk, d);
                int op = __shfl_down_sync(0xffffffffu, bp, d);
                if (ok > bk) { bk = ok; bp = op; }
            }
            if (t == 0) {
                int valid = ((unsigned)(bk >> 32) > vthr) ? 1 : 0;
                curvalid = valid;
                curpos = bp;
                if (valid) {
                    float4 b = B[bp];
                    curbox = b;
                    cura = A[bp];
                    out[it * 4 + 0] = b.x;
                    out[it * 4 + 1] = b.y;
                    out[it * 4 + 2] = b.z;
                    out[it * 4 + 3] = b.w;
                } else {
                    out[it * 4 + 0] = 0.f;
                    out[it * 4 + 1] = 0.f;
                    out[it * 4 + 2] = 0.f;
                    out[it * 4 + 3] = 0.f;
                }
            }
        }
        __syncthreads();
        if (curvalid) {
            float4 bb = curbox;
            float a1 = cura;
            int cp = curpos;
            lbk = 0ull;
            lbp = t;
#pragma unroll
            for (int k = 0; k < 6; k++) {
                int i = k * 1024 + t;
                float4 c = bx[k];
                float ty = fmaxf(bb.x, c.x);
                float tx = fmaxf(bb.y, c.y);
                float by = fminf(bb.z, c.z);
                float bxx = fminf(bb.w, c.w);
                float inter = __fmul_rn(fmaxf(__fadd_rn(by, -ty), 0.f),
                                        fmaxf(__fadd_rn(bxx, -tx), 0.f));
                bool kill = (i == cp);
                if (inter > 0.f) {
                    float iou = __fdiv_rn(inter,
                        fmaxf(__fadd_rn(__fadd_rn(a1, ar[k]), -inter), 1e-9f));
                    kill = kill || (iou > 0.7f);
                }
                if (kill) key[k] = deadhi | (key[k] & 0xFFFFFFFFull);
                if (key[k] > lbk) { lbk = key[k]; lbp = i; }
            }
        }
        // no extra barrier: next iteration's first barrier orders rk/rp reuse
    }
}

// ---------------- host launcher ----------------
extern "C" void kernel_launch(void* const* d_in, const int* in_sizes, int n_in,
                              void* d_out, int out_size)
{
    (void)in_sizes; (void)n_in; (void)out_size;
    const float* p2 = (const float*)d_in[0];
    const float* p3 = (const float*)d_in[1];
    const float* p4 = (const float*)d_in[2];
    const float* p5 = (const float*)d_in[3];
    const float* p6 = (const float*)d_in[4];
    const float* conv_w  = (const float*)d_in[5];
    const float* conv_b  = (const float*)d_in[6];
    const float* loc_w   = (const float*)d_in[7];
    const float* loc_b   = (const float*)d_in[8];
    const float* score_w = (const float*)d_in[9];
    const float* score_b = (const float*)d_in[10];
    float* out = (float*)d_out;

    cudaFuncSetAttribute(w2_gemm_k, cudaFuncAttributeMaxDynamicSharedMemorySize, W2_SMEM);
    cudaFuncSetAttribute(nms_kernel, cudaFuncAttributeMaxDynamicSharedMemorySize, (int)NMS_SMEM);

    w0_wtrans<<<256, 256>>>(conv_w);                         // launch 0
    dummy_k<<<1, 32>>>();                                    // launch 1
    dummy_k<<<1, 32>>>();                                    // launch 2
    w1_xtrans<<<dim3(341, 64), 256>>>(p2, p3, p4, p5, p6);   // launch 3 <- ncu capture slot
    w2_gemm_k<<<dim3(341, 16), 256, W2_SMEM>>>();
    w3_otrans<<<dim3(341, 16), 256>>>(conv_b);

    heads_decode<<<341, 128>>>(loc_w, loc_b, score_w, score_b);

    topk_init<<<1, 256>>>();
    const int shifts[4] = {24, 16, 8, 0};
    const unsigned int masks[4] = {0x00000000u, 0xFF000000u, 0xFFFF0000u, 0xFFFFFF00u};
    for (int p = 0; p < 4; p++) {
        topk_hist<<<512, 256>>>(shifts[p], masks[p]);
        topk_select<<<1, 256>>>(shifts[p]);
    }
    topk_compact<<<512, 256>>>();
    topk_ties<<<1, 1024>>>();

    nms_kernel<<<1, 1024, NMS_SMEM>>>(out);
}

// round 14
// speedup vs baseline: 1.0577x; 1.0059x over previous
#include <cuda_runtime.h>
#include <math.h>

#define HTOT 87296
#define NANCH 261888
#define PRE_NMS_N 6000
#define POST_NMS_N 300
#define NEGV -1000000000.0f
#define TIE_CAP 16384
#define STTOT 21824

typedef unsigned long long u64;
typedef unsigned int u32;

// ---------------- device scratch ----------------
static __device__ __align__(16) float g_h[(size_t)256 * HTOT];
static __device__ __align__(16) float g_V[(size_t)16 * 256 * STTOT];  // winograd V; reused in-place as M
static __device__ __align__(16) float g_U[(size_t)16 * 256 * 256];    // transformed weights (scalar, no dup)
#define g_M g_V   // safe alias: w2 block (stb,k) reads V[k][:,st-tile] fully before writing M[k][:,st-tile]
static __device__ float4 g_boxes[NANCH];
static __device__ float  g_scores[NANCH];
static __device__ float4 g_tb[PRE_NMS_N];
static __device__ float  g_ts[PRE_NMS_N];
static __device__ int    g_ti[PRE_NMS_N];
static __device__ unsigned int g_hist[256];
static __device__ unsigned int g_prefix, g_above, g_remain;
static __device__ int g_ctr, g_tiectr;
static __device__ int g_ties[TIE_CAP];

// ---------------- f32x2 / cp.async helpers ----------------
__device__ __forceinline__ void ffma2(u64& d, u64 a, u64 b) {
    asm("fma.rn.f32x2 %0, %1, %2, %0;" : "+l"(d) : "l"(a), "l"(b));
}
__device__ __forceinline__ u64 dup2(float v) {
    u64 r;
    asm("mov.b64 %0, {%1, %2};" : "=l"(r) : "f"(v), "f"(v));
    return r;
}
__device__ __forceinline__ void cpasync16(u32 saddr, const void* gptr) {
    asm volatile("cp.async.cg.shared.global [%0], [%1], 16;" :: "r"(saddr), "l"(gptr));
}
__device__ __forceinline__ void cp_commit() {
    asm volatile("cp.async.commit_group;");
}

// ---------------- W0: weight transform U = G w G^T (scalar layout) ------
__global__ __launch_bounds__(256) void w0_wtrans(const float* __restrict__ w) {
    int oc = blockIdx.x;
    int ic = threadIdx.x;
    const float* g = w + ((size_t)oc * 256 + ic) * 9;
    float g0 = g[0], g1 = g[1], g2 = g[2];
    float g3 = g[3], g4 = g[4], g5 = g[5];
    float g6 = g[6], g7 = g[7], g8 = g[8];

    float T[4][3];
    T[0][0] = g0; T[0][1] = g1; T[0][2] = g2;
    T[1][0] = 0.5f * (g0 + g3 + g6); T[1][1] = 0.5f * (g1 + g4 + g7); T[1][2] = 0.5f * (g2 + g5 + g8);
    T[2][0] = 0.5f * (g0 - g3 + g6); T[2][1] = 0.5f * (g1 - g4 + g7); T[2][2] = 0.5f * (g2 - g5 + g8);
    T[3][0] = g6; T[3][1] = g7; T[3][2] = g8;

#pragma unroll
    for (int r = 0; r < 4; r++) {
        float u0 = T[r][0];
        float u1 = 0.5f * (T[r][0] + T[r][1] + T[r][2]);
        float u2 = 0.5f * (T[r][0] - T[r][1] + T[r][2]);
        float u3 = T[r][2];
        float uv[4] = {u0, u1, u2, u3};
#pragma unroll
        for (int c = 0; c < 4; c++) {
            int k = r * 4 + c;
            g_U[((size_t)k * 256 + ic) * 256 + oc] = uv[c];
        }
    }
}

// ---------------- W1: input transform V = B^T d B (per-thread LDG) -------
__global__ __launch_bounds__(256) void w1_xtrans(
    const float* __restrict__ p2, const float* __restrict__ p3,
    const float* __restrict__ p4, const float* __restrict__ p5,
    const float* __restrict__ p6)
{
    int stb = blockIdx.x;          // 0..340
    int icg = blockIdx.y;          // 0..63
    int t = threadIdx.x;
    int stl = t & 63;
    int icl = t >> 6;
    int st0 = stb * 64;

    const float* x; int W, lsw, stoff;
    if (st0 < 16384)       { x = p2; W = 256; lsw = 7; stoff = 0; }
    else if (st0 < 20480)  { x = p3; W = 128; lsw = 6; stoff = 16384; }
    else if (st0 < 21504)  { x = p4; W = 64;  lsw = 5; stoff = 20480; }
    else if (st0 < 21760)  { x = p5; W = 32;  lsw = 4; stoff = 21504; }
    else                   { x = p6; W = 16;  lsw = 3; stoff = 21760; }
    int SW = W >> 1;

    int ic = icg * 4 + icl;
    int st = st0 + stl;
    int sidx = st - stoff;
    int sy = sidx >> lsw;
    int sx = sidx & (SW - 1);
    int py = 2 * sy - 1;
    int px = 2 * sx - 1;
    const float* xp = x + (size_t)ic * W * W;

    float d[4][4];
#pragma unroll
    for (int r = 0; r < 4; r++) {
        int yy = py + r;
        bool yok = (yy >= 0) && (yy < W);
#pragma unroll
        for (int c = 0; c < 4; c++) {
            int xx = px + c;
            d[r][c] = (yok && xx >= 0 && xx < W) ? xp[yy * W + xx] : 0.f;
        }
    }
    float e[4][4];
#pragma unroll
    for (int c = 0; c < 4; c++) {
        e[0][c] = d[0][c] - d[2][c];
        e[1][c] = d[1][c] + d[2][c];
        e[2][c] = d[2][c] - d[1][c];
        e[3][c] = d[1][c] - d[3][c];
    }
    float V[4][4];
#pragma unroll
    for (int r = 0; r < 4; r++) {
        V[r][0] = e[r][0] - e[r][2];
        V[r][1] = e[r][1] + e[r][2];
        V[r][2] = e[r][2] - e[r][1];
        V[r][3] = e[r][1] - e[r][3];
    }
    size_t base = (size_t)ic * STTOT + st;
#pragma unroll
    for (int r = 0; r < 4; r++)
#pragma unroll
        for (int c = 0; c < 4; c++)
            g_V[(size_t)(r * 4 + c) * 256 * STTOT + base] = V[r][c];
}

// ---------------- W2: pure GEMM per k, double-buffered cp.async ----------
// block = (stb, k): 256 oc x 64 st x 256 ic. thread = 8 oc x 8 st.
// buffer: V 16x64 (4KB) + U 16x256 scalar (16KB) = 5120 floats; 2 buffers.
#define W2_BUF 5120
#define W2_SMEM (2 * W2_BUF * 4)

__global__ __launch_bounds__(256, 2) void w2_gemm_k() {
    extern __shared__ __align__(16) float sm[];

    const int t   = threadIdx.x;
    const int stb = blockIdx.x;    // 0..340
    const int k   = blockIdx.y;    // 0..15
    const int st0 = stb * 64;
    const int thr_oc = t >> 3;     // 0..31
    const int thr_st = t & 7;      // 0..7

    u64 m[8][4];
#pragma unroll
    for (int o = 0; o < 8; o++)
#pragma unroll
        for (int s = 0; s < 4; s++) m[o][s] = 0ull;

    const float* Vbase = g_V + (size_t)k * 256 * STTOT + st0;
    const float* Ubase = g_U + (size_t)k * 256 * 256;

    // staging mapping
    const int vr = t >> 4;              // ic-local 0..15
    const int vcofs = (t & 15) * 4;     // col 0..60

    u32 smbase = (u32)__cvta_generic_to_shared(sm);

#define W2_PREFETCH(chunk, buf)                                                  \
    do {                                                                         \
        u32 bs_ = smbase + (buf) * (W2_BUF * 4);                                 \
        cpasync16(bs_ + (vr * 64 + vcofs) * 4,                                   \
                  Vbase + (size_t)((chunk) * 16 + vr) * STTOT + vcofs);          \
        const float* us_ = Ubase + (size_t)(chunk) * 16 * 256;                   \
        u32 ud_ = bs_ + 1024 * 4;                                                \
        _Pragma("unroll")                                                        \
        for (int j = 0; j < 4; j++)                                              \
            cpasync16(ud_ + (t + j * 256) * 16, us_ + (size_t)(t + j * 256) * 4);\
        cp_commit();                                                             \
    } while (0)

    W2_PREFETCH(0, 0);
    W2_PREFETCH(1, 1);

    for (int c = 0; c < 16; c++) {
        if (c < 15) asm volatile("cp.async.wait_group 1;");
        else        asm volatile("cp.async.wait_group 0;");
        __syncthreads();

        const float* bs = sm + (c & 1) * W2_BUF;
        const float* Vc = bs;
        const float* Uc = bs + 1024;
#pragma unroll
        for (int ic = 0; ic < 16; ic++) {
            const ulonglong2* vp = (const ulonglong2*)(Vc + ic * 64 + thr_st * 8);
            ulonglong2 va = vp[0], vb = vp[1];
            u64 v[4] = {va.x, va.y, vb.x, vb.y};
            const float4* up = (const float4*)(Uc + ic * 256 + thr_oc * 8);
            float4 ua4 = up[0], ub4 = up[1];
            u64 u[8];
            u[0] = dup2(ua4.x); u[1] = dup2(ua4.y);
            u[2] = dup2(ua4.z); u[3] = dup2(ua4.w);
            u[4] = dup2(ub4.x); u[5] = dup2(ub4.y);
            u[6] = dup2(ub4.z); u[7] = dup2(ub4.w);
#pragma unroll
            for (int o = 0; o < 8; o++)
#pragma unroll
                for (int s = 0; s < 4; s++) ffma2(m[o][s], v[s], u[o]);
        }
        __syncthreads();
        if (c + 2 < 16) W2_PREFETCH(c + 2, c & 1);
    }

    // all V reads for this (k, st-tile) are done; in-place write M over V
#pragma unroll
    for (int o = 0; o < 8; o++) {
        int oc = thr_oc * 8 + o;
        u64* mp = (u64*)(g_M + ((size_t)k * 256 + oc) * STTOT + st0 + thr_st * 8);
        ulonglong2 s0, s1;
        s0.x = m[o][0]; s0.y = m[o][1];
        s1.x = m[o][2]; s1.y = m[o][3];
        *(ulonglong2*)mp = s0;
        *(ulonglong2*)(mp + 2) = s1;
    }
}

// ---------------- W3: output transform A^T M A + bias + relu (st-pairs) ---
__global__ __launch_bounds__(256) void w3_otrans(const float* __restrict__ bias) {
    const int stb = blockIdx.x;    // 0..340
    const int ocg = blockIdx.y;    // 0..15
    const int t = threadIdx.x;
    const int stp = t & 31;        // st-pair index 0..31
    const int ocl = t >> 5;        // 0..7
    const int st0 = stb * 64;
    const int st  = st0 + stp * 2;

    int W, lsw, stoff, pixoff;
    if (st0 < 16384)       { W = 256; lsw = 7; stoff = 0;     pixoff = 0; }
    else if (st0 < 20480)  { W = 128; lsw = 6; stoff = 16384; pixoff = 65536; }
    else if (st0 < 21504)  { W = 64;  lsw = 5; stoff = 20480; pixoff = 81920; }
    else if (st0 < 21760)  { W = 32;  lsw = 4; stoff = 21504; pixoff = 86016; }
    else                   { W = 16;  lsw = 3; stoff = 21760; pixoff = 87040; }
    int SW = W >> 1;

    int sidx = st - stoff;     // even; sidx and sidx+1 share the row (SW even)
    int sy = sidx >> lsw;
    int sx = sidx & (SW - 1);

#pragma unroll
    for (int o2 = 0; o2 < 2; o2++) {
        int oc = ocg * 16 + ocl * 2 + o2;
        const float2* Mp = (const float2*)(g_M + (size_t)oc * STTOT + st);
        float2 Mv[16];
#pragma unroll
        for (int kk = 0; kk < 16; kk++)
            Mv[kk] = Mp[(size_t)kk * 128 * STTOT];   // stride 256*STTOT floats = 128*STTOT float2

        float e0x[4], e1x[4], e0y[4], e1y[4];
#pragma unroll
        for (int c = 0; c < 4; c++) {
            e0x[c] = Mv[c].x + Mv[4 + c].x + Mv[8 + c].x;
            e1x[c] = Mv[4 + c].x - Mv[8 + c].x - Mv[12 + c].x;
            e0y[c] = Mv[c].y + Mv[4 + c].y + Mv[8 + c].y;
            e1y[c] = Mv[4 + c].y - Mv[8 + c].y - Mv[12 + c].y;
        }
        float bv = bias[oc];
        float4 r0, r1;
        r0.x = fmaxf((e0x[0] + e0x[1] + e0x[2]) + bv, 0.f);
        r0.y = fmaxf((e0x[1] - e0x[2] - e0x[3]) + bv, 0.f);
        r0.z = fmaxf((e0y[0] + e0y[1] + e0y[2]) + bv, 0.f);
        r0.w = fmaxf((e0y[1] - e0y[2] - e0y[3]) + bv, 0.f);
        r1.x = fmaxf((e1x[0] + e1x[1] + e1x[2]) + bv, 0.f);
        r1.y = fmaxf((e1x[1] - e1x[2] - e1x[3]) + bv, 0.f);
        r1.z = fmaxf((e1y[0] + e1y[1] + e1y[2]) + bv, 0.f);
        r1.w = fmaxf((e1y[1] - e1y[2] - e1y[3]) + bv, 0.f);

        float* hp = g_h + (size_t)oc * HTOT + pixoff;
        *(float4*)&hp[(2 * sy) * W + 2 * sx]     = r0;
        *(float4*)&hp[(2 * sy + 1) * W + 2 * sx] = r1;
    }
}

// ---------------- heads: 1x1 convs + softmax + decode, 2 px/thread -------
__global__ __launch_bounds__(128) void heads_decode(
    const float* __restrict__ lw, const float* __restrict__ lb,
    const float* __restrict__ sw, const float* __restrict__ sb)
{
    __shared__ float WL[12][256];
    __shared__ float WS[6][256];
    __shared__ float BL[12], BS[6];
    const int t = threadIdx.x;
    for (int i = t; i < 12 * 256; i += 128) WL[i >> 8][i & 255] = lw[i];
    for (int i = t; i < 6 * 256; i += 128)  WS[i >> 8][i & 255] = sw[i];
    if (t < 12) BL[t] = lb[t];
    if (t < 6)  BS[t] = sb[t];
    __syncthreads();

    const int pix0 = (blockIdx.x * 128 + t) * 2;   // even; both pixels same level/row
    int lvl;
    if (pix0 < 65536) lvl = 0;
    else if (pix0 < 81920) lvl = 1;
    else if (pix0 < 86016) lvl = 2;
    else if (pix0 < 87040) lvl = 3;
    else lvl = 4;
    const int offs[5] = {0, 65536, 81920, 86016, 87040};
    const int lp   = pix0 - offs[lvl];
    const int lw2  = 8 - lvl;
    const int row  = lp >> lw2;
    const int col0 = lp & ((1 << lw2) - 1);
    const int strd = 4 << lvl;

    float acc[2][18];
#pragma unroll
    for (int p = 0; p < 2; p++) {
#pragma unroll
        for (int j = 0; j < 12; j++) acc[p][j] = BL[j];
#pragma unroll
        for (int j = 0; j < 6; j++)  acc[p][12 + j] = BS[j];
    }

    const float* hp = g_h + pix0;
#pragma unroll 8
    for (int ic = 0; ic < 256; ic++) {
        float2 v = *(const float2*)(hp + (size_t)ic * HTOT);
#pragma unroll
        for (int j = 0; j < 12; j++) {
            float wv = WL[j][ic];
            acc[0][j] = fmaf(wv, v.x, acc[0][j]);
            acc[1][j] = fmaf(wv, v.y, acc[1][j]);
        }
#pragma unroll
        for (int j = 0; j < 6; j++) {
            float wv = WS[j][ic];
            acc[0][12 + j] = fmaf(wv, v.x, acc[0][12 + j]);
            acc[1][12 + j] = fmaf(wv, v.y, acc[1][12 + j]);
        }
    }

    const float sr[3] = {0.70710678118654752f, 1.0f, 1.41421356237309505f};
#pragma unroll
    for (int p = 0; p < 2; p++) {
        const int pix = pix0 + p;
        const float y  = (float)(row * strd);
        const float xx = (float)((col0 + p) * strd);
#pragma unroll
        for (int a = 0; a < 3; a++) {
            float hs = (float)(strd * 8) * sr[a];
            float ws = (float)(strd * 8) * sr[2 - a];
            float a0 = __fadd_rn(y,  -0.5f * hs);
            float a1 = __fadd_rn(xx, -0.5f * ws);
            float a2 = __fadd_rn(y,   0.5f * hs);
            float a3 = __fadd_rn(xx,  0.5f * ws);
            float ah = __fadd_rn(a2, -a0);
            float aw = __fadd_rn(a3, -a1);
            float acy = __fadd_rn(a0, __fmul_rn(0.5f, ah));
            float acx = __fadd_rn(a1, __fmul_rn(0.5f, aw));
            float dy = acc[p][a * 4 + 0], dx = acc[p][a * 4 + 1];
            float dh = acc[p][a * 4 + 2], dw = acc[p][a * 4 + 3];
            float cy = __fadd_rn(__fmul_rn(dy, ah), acy);
            float cx = __fadd_rn(__fmul_rn(dx, aw), acx);
            float bh = __fmul_rn(expf(dh), ah);
            float bw = __fmul_rn(expf(dw), aw);
            float b0 = fminf(fmaxf(__fadd_rn(cy, -__fmul_rn(0.5f, bh)), 0.f), 1024.f);
            float b1 = fminf(fmaxf(__fadd_rn(cx, -__fmul_rn(0.5f, bw)), 0.f), 1024.f);
            float b2 = fminf(fmaxf(__fadd_rn(cy,  __fmul_rn(0.5f, bh)), 0.f), 1024.f);
            float b3 = fminf(fmaxf(__fadd_rn(cx,  __fmul_rn(0.5f, bw)), 0.f), 1024.f);

            float s0 = acc[p][12 + a * 2], s1 = acc[p][12 + a * 2 + 1];
            float mm = fmaxf(s0, s1);
            float e0 = expf(__fadd_rn(s0, -mm));
            float e1 = expf(__fadd_rn(s1, -mm));
            float fg = __fdiv_rn(e1, __fadd_rn(e0, e1));

            float hh  = __fadd_rn(b2, -b0);
            float ww2 = __fadd_rn(b3, -b1);
            float scv = (hh >= 16.f && ww2 >= 16.f) ? fg : NEGV;

            int aid = pix * 3 + a;
            g_boxes[aid]  = make_float4(b0, b1, b2, b3);
            g_scores[aid] = scv;
        }
    }
}

// ---------------- exact top-6000 via 4-pass radix select ----------------
__device__ __forceinline__ unsigned int fkey(float f) {
    unsigned int u = __float_as_uint(f);
    return u ^ ((u & 0x80000000u) ? 0xFFFFFFFFu : 0x80000000u);
}

__global__ void topk_init() {
    int t = threadIdx.x;
    if (t < 256) g_hist[t] = 0;
    if (t == 0) { g_prefix = 0; g_above = 0; g_remain = PRE_NMS_N; g_ctr = 0; g_tiectr = 0; }
}

__global__ void topk_hist(int shift, unsigned int mask) {
    __shared__ unsigned int sh[256];
    if (threadIdx.x < 256) sh[threadIdx.x] = 0;
    __syncthreads();
    unsigned int pref = g_prefix;
    for (int i = blockIdx.x * blockDim.x + threadIdx.x; i < NANCH; i += gridDim.x * blockDim.x) {
        unsigned int k = fkey(g_scores[i]);
        if ((k & mask) == (pref & mask)) atomicAdd(&sh[(k >> shift) & 255u], 1u);
    }
    __syncthreads();
    if (threadIdx.x < 256 && sh[threadIdx.x]) atomicAdd(&g_hist[threadIdx.x], sh[threadIdx.x]);
}

__global__ void topk_select(int shift) {
    __shared__ unsigned int h[256];
    int t = threadIdx.x;
    h[t] = g_hist[t];
    __syncthreads();
    if (t == 0) {
        unsigned int remain = g_remain;
        unsigned int cum = 0;
        int b = 255;
        for (; b > 0; b--) {
            if (cum + h[b] >= remain) break;
            cum += h[b];
        }
        g_above  = g_above + cum;
        g_remain = remain - cum;
        g_prefix = g_prefix | ((unsigned int)b << shift);
    }
    __syncthreads();
    g_hist[t] = 0;
}

__global__ void topk_compact() {
    unsigned int kt = g_prefix;
    for (int i = blockIdx.x * blockDim.x + threadIdx.x; i < NANCH; i += gridDim.x * blockDim.x) {
        float s = g_scores[i];
        unsigned int k = fkey(s);
        if (k > kt) {
            int p = atomicAdd(&g_ctr, 1);
            g_tb[p] = g_boxes[i];
            g_ts[p] = s;
            g_ti[p] = i;
        } else if (k == kt) {
            int p = atomicAdd(&g_tiectr, 1);
            if (p < TIE_CAP) g_ties[p] = i;
        }
    }
}

__global__ void topk_ties() {
    int need = (int)g_remain;
    int base = (int)g_above;
    int M = g_tiectr;
    if (M > TIE_CAP) M = TIE_CAP;
    for (int i = threadIdx.x; i < M; i += blockDim.x) {
        int idx = g_ties[i];
        int rank = 0;
        for (int j = 0; j < M; j++) rank += (g_ties[j] < idx) ? 1 : 0;
        if (rank < need) {
            int p = base + rank;
            g_tb[p] = g_boxes[idx];
            g_ts[p] = g_scores[idx];
            g_ti[p] = idx;
        }
    }
}

// ---------------- sequential NMS: fused suppress+argmax, 2 barriers/iter --
#define NMS_SMEM (PRE_NMS_N * (sizeof(float4) + sizeof(float)))

__global__ __launch_bounds__(1024) void nms_kernel(float* __restrict__ out) {
    extern __shared__ char nsm[];
    float4* B = (float4*)nsm;
    float*  A = (float*)(B + PRE_NMS_N);
    __shared__ u64 rk[32];
    __shared__ int rp[32];
    __shared__ float4 curbox;
    __shared__ float cura;
    __shared__ int curpos, curvalid;

    const int t = threadIdx.x;
    float4 bx[6];
    float  ar[6];
    u64    key[6];

#pragma unroll
    for (int k = 0; k < 6; k++) {
        int i = k * 1024 + t;
        if (i < PRE_NMS_N) {
            float4 b = g_tb[i];
            float a = __fmul_rn(__fadd_rn(b.z, -b.x), __fadd_rn(b.w, -b.y));
            bx[k] = b;
            ar[k] = a;
            key[k] = ((u64)fkey(g_ts[i]) << 32) | (u64)(unsigned)(~(unsigned)g_ti[i]);
            B[i] = b;
            A[i] = a;
        } else {
            bx[k] = make_float4(0.f, 0.f, 0.f, 0.f);
            ar[k] = 0.f;
            key[k] = 0ull;
        }
    }
    const unsigned vthr = fkey(NEGV * 0.5f);
    const u64 deadhi = ((u64)fkey(NEGV)) << 32;

    u64 lbk = key[0];
    int lbp = t;
#pragma unroll
    for (int k = 1; k < 6; k++)
        if (key[k] > lbk) { lbk = key[k]; lbp = k * 1024 + t; }
    __syncthreads();

    for (int it = 0; it < POST_NMS_N; it++) {
        u64 bk = lbk;
        int bp = lbp;
#pragma unroll
        for (int d = 16; d > 0; d >>= 1) {
            u64 ok = __shfl_down_sync(0xffffffffu, bk, d);
            int op = __shfl_down_sync(0xffffffffu, bp, d);
            if (ok > bk) { bk = ok; bp = op; }
        }
        if ((t & 31) == 0) { rk[t >> 5] = bk; rp[t >> 5] = bp; }
        __syncthreads();
        if (t < 32) {
            bk = rk[t]; bp = rp[t];
#pragma unroll
            for (int d = 16; d > 0; d >>= 1) {
                u64 ok = __shfl_down_sync(0xffffffffu, bk, d);
                int op = __shfl_down_sync(0xffffffffu, bp, d);
                if (ok > bk) { bk = ok; bp = op; }
            }
            if (t == 0) {
                int valid = ((unsigned)(bk >> 32) > vthr) ? 1 : 0;
                curvalid = valid;
                curpos = bp;
                if (valid) {
                    float4 b = B[bp];
                    curbox = b;
                    cura = A[bp];
                    out[it * 4 + 0] = b.x;
                    out[it * 4 + 1] = b.y;
                    out[it * 4 + 2] = b.z;
                    out[it * 4 + 3] = b.w;
                } else {
                    out[it * 4 + 0] = 0.f;
                    out[it * 4 + 1] = 0.f;
                    out[it * 4 + 2] = 0.f;
                    out[it * 4 + 3] = 0.f;
                }
            }
        }
        __syncthreads();
        if (curvalid) {
            float4 bb = curbox;
            float a1 = cura;
            int cp = curpos;
            lbk = 0ull;
            lbp = t;
#pragma unroll
            for (int k = 0; k < 6; k++) {
                int i = k * 1024 + t;
                float4 c = bx[k];
                float ty = fmaxf(bb.x, c.x);
                float tx = fmaxf(bb.y, c.y);
                float by = fminf(bb.z, c.z);
                float bxx = fminf(bb.w, c.w);
                float inter = __fmul_rn(fmaxf(__fadd_rn(by, -ty), 0.f),
                                        fmaxf(__fadd_rn(bxx, -tx), 0.f));
                bool kill = (i == cp);
                if (inter > 0.f) {
                    float iou = __fdiv_rn(inter,
                        fmaxf(__fadd_rn(__fadd_rn(a1, ar[k]), -inter), 1e-9f));
                    kill = kill || (iou > 0.7f);
                }
                if (kill) key[k] = deadhi | (key[k] & 0xFFFFFFFFull);
                if (key[k] > lbk) { lbk = key[k]; lbp = i; }
            }
        }
    }
}

// ---------------- host launcher ----------------
extern "C" void kernel_launch(void* const* d_in, const int* in_sizes, int n_in,
                              void* d_out, int out_size)
{
    (void)in_sizes; (void)n_in; (void)out_size;
    const float* p2 = (const float*)d_in[0];
    const float* p3 = (const float*)d_in[1];
    const float* p4 = (const float*)d_in[2];
    const float* p5 = (const float*)d_in[3];
    const float* p6 = (const float*)d_in[4];
    const float* conv_w  = (const float*)d_in[5];
    const float* conv_b  = (const float*)d_in[6];
    const float* loc_w   = (const float*)d_in[7];
    const float* loc_b   = (const float*)d_in[8];
    const float* score_w = (const float*)d_in[9];
    const float* score_b = (const float*)d_in[10];
    float* out = (float*)d_out;

    cudaFuncSetAttribute(w2_gemm_k, cudaFuncAttributeMaxDynamicSharedMemorySize, W2_SMEM);
    cudaFuncSetAttribute(nms_kernel, cudaFuncAttributeMaxDynamicSharedMemorySize, (int)NMS_SMEM);

    w0_wtrans<<<256, 256>>>(conv_w);                         // launch 0
    w1_xtrans<<<dim3(341, 64), 256>>>(p2, p3, p4, p5, p6);   // launch 1
    w2_gemm_k<<<dim3(341, 16), 256, W2_SMEM>>>();            // launch 2
    w3_otrans<<<dim3(341, 16), 256>>>(conv_b);               // launch 3 <- ncu capture slot

    heads_decode<<<341, 128>>>(loc_w, loc_b, score_w, score_b);

    topk_init<<<1, 256>>>();
    const int shifts[4] = {24, 16, 8, 0};
    const unsigned int masks[4] = {0x00000000u, 0xFF000000u, 0xFFFF0000u, 0xFFFFFF00u};
    for (int p = 0; p < 4; p++) {
        topk_hist<<<512, 256>>>(shifts[p], masks[p]);
        topk_select<<<1, 256>>>(shifts[p]);
    }
    topk_compact<<<512, 256>>>();
    topk_ties<<<1, 1024>>>();

    nms_kernel<<<1, 1024, NMS_SMEM>>>(out);
}